// round 1
// baseline (speedup 1.0000x reference)
#include <cuda_runtime.h>
#include <math.h>

// Problem constants
#define BB   8
#define NN_  1024
#define CC   1024
#define HH   16
#define DD   64
#define TT   16
#define HID  4096
#define MROWS (BB * NN_)   // 8192

// ---------------- scratch (static device globals; no allocation allowed) ----
__device__ float g_h  [(size_t)MROWS * CC];          // LN output (reused)
__device__ float g_qkv[(size_t)MROWS * 3 * CC];      // qkv matmul out
__device__ float g_q  [(size_t)BB * HH * NN_ * DD];
__device__ float g_k  [(size_t)BB * HH * NN_ * DD];
__device__ float g_v  [(size_t)BB * HH * NN_ * DD];
__device__ float g_s  [(size_t)BB * HH * NN_ * NN_]; // attention scores (512MB)
__device__ float g_o  [(size_t)BB * HH * NN_ * DD];
__device__ float g_o2 [(size_t)MROWS * CC];
__device__ float g_y  [(size_t)MROWS * HID];
__device__ float g_w1 [(size_t)HID * CC];
__device__ float g_w2 [(size_t)CC * HID];

// ---------------- LayerNorm: one block per row of 1024 ----------------------
__global__ void ln_kernel(const float* __restrict__ x, const float* __restrict__ g,
                          const float* __restrict__ b, float* __restrict__ out)
{
    __shared__ float sh1[8], sh2[8];
    int row = blockIdx.x;
    int tid = threadIdx.x;
    const float* p = x + (size_t)row * 1024;
    float v[4];
    float s = 0.f, sq = 0.f;
#pragma unroll
    for (int j = 0; j < 4; j++) {
        v[j] = p[tid + j * 256];
        s += v[j];
        sq += v[j] * v[j];
    }
#pragma unroll
    for (int o = 16; o > 0; o >>= 1) {
        s  += __shfl_xor_sync(0xffffffffu, s,  o);
        sq += __shfl_xor_sync(0xffffffffu, sq, o);
    }
    if ((tid & 31) == 0) { sh1[tid >> 5] = s; sh2[tid >> 5] = sq; }
    __syncthreads();
    if (tid == 0) {
        float a = 0.f, c = 0.f;
        for (int i = 0; i < 8; i++) { a += sh1[i]; c += sh2[i]; }
        sh1[0] = a; sh2[0] = c;
    }
    __syncthreads();
    float mean = sh1[0] * (1.f / 1024.f);
    float var  = sh2[0] * (1.f / 1024.f) - mean * mean;
    float rstd = rsqrtf(var + 1e-5f);
    float* q = out + (size_t)row * 1024;
#pragma unroll
    for (int j = 0; j < 4; j++) {
        int i = tid + j * 256;
        q[i] = (v[j] - mean) * rstd * g[i] + b[i];
    }
}

// ---------------- row softmax: one block per row of 1024 --------------------
__global__ void softmax_kernel(float* __restrict__ S)
{
    __shared__ float sh[8];
    size_t row = blockIdx.x;
    float* p = S + row * 1024;
    int tid = threadIdx.x;
    float v[4];
    float m = -1e30f;
#pragma unroll
    for (int j = 0; j < 4; j++) {
        v[j] = p[tid + j * 256];
        m = fmaxf(m, v[j]);
    }
#pragma unroll
    for (int o = 16; o > 0; o >>= 1)
        m = fmaxf(m, __shfl_xor_sync(0xffffffffu, m, o));
    if ((tid & 31) == 0) sh[tid >> 5] = m;
    __syncthreads();
    if (tid == 0) {
        float a = sh[0];
        for (int i = 1; i < 8; i++) a = fmaxf(a, sh[i]);
        sh[0] = a;
    }
    __syncthreads();
    m = sh[0];
    __syncthreads();   // protect sh before sum-reduce reuse
    float s = 0.f;
#pragma unroll
    for (int j = 0; j < 4; j++) {
        v[j] = expf(v[j] - m);
        s += v[j];
    }
#pragma unroll
    for (int o = 16; o > 0; o >>= 1)
        s += __shfl_xor_sync(0xffffffffu, s, o);
    if ((tid & 31) == 0) sh[tid >> 5] = s;
    __syncthreads();
    if (tid == 0) {
        float a = 0.f;
        for (int i = 0; i < 8; i++) a += sh[i];
        sh[0] = a;
    }
    __syncthreads();
    float inv = 1.f / sh[0];
#pragma unroll
    for (int j = 0; j < 4; j++)
        p[tid + j * 256] = v[j] * inv;
}

// ---------------- tiled SGEMM, C = alpha*(A @ B^T), B row-major [N,K] -------
// 64x64 tile, BK=16, 256 threads, 4x4 per thread. All dims assumed divisible.
// Epilogue: +bias[n] (opt), GELU (opt), +res (opt). Batched via strides/grid.z.
__global__ void gemm_nt(const float* __restrict__ A, const float* __restrict__ Bm,
                        float* __restrict__ C, const float* __restrict__ res,
                        const float* __restrict__ bias,
                        int M, int N, int K,
                        long long sA, long long sB, long long sC,
                        float alpha, int act)
{
    __shared__ float As[16][64];
    __shared__ float Bs[16][64];
    int bz = blockIdx.z;
    A  += (size_t)bz * sA;
    Bm += (size_t)bz * sB;
    C  += (size_t)bz * sC;
    if (res) res += (size_t)bz * sC;

    int tid = threadIdx.x;
    int lr = tid >> 2;          // 0..63
    int lc = (tid & 3) << 2;    // 0,4,8,12
    const float* Ap = A  + (size_t)(blockIdx.y * 64 + lr) * K + lc;
    const float* Bp = Bm + (size_t)(blockIdx.x * 64 + lr) * K + lc;
    int ty = tid >> 4, tx = tid & 15;
    float acc[4][4] = {};

    for (int k0 = 0; k0 < K; k0 += 16) {
        float4 a4 = *(const float4*)(Ap + k0);
        float4 b4 = *(const float4*)(Bp + k0);
        As[lc + 0][lr] = a4.x; As[lc + 1][lr] = a4.y;
        As[lc + 2][lr] = a4.z; As[lc + 3][lr] = a4.w;
        Bs[lc + 0][lr] = b4.x; Bs[lc + 1][lr] = b4.y;
        Bs[lc + 2][lr] = b4.z; Bs[lc + 3][lr] = b4.w;
        __syncthreads();
#pragma unroll
        for (int k = 0; k < 16; k++) {
            float4 ra = *(const float4*)&As[k][ty << 2];
            float4 rb = *(const float4*)&Bs[k][tx << 2];
            float a[4] = {ra.x, ra.y, ra.z, ra.w};
            float b[4] = {rb.x, rb.y, rb.z, rb.w};
#pragma unroll
            for (int i = 0; i < 4; i++)
#pragma unroll
                for (int j = 0; j < 4; j++)
                    acc[i][j] += a[i] * b[j];
        }
        __syncthreads();
    }

    int r0 = blockIdx.y * 64 + (ty << 2);
    int c0 = blockIdx.x * 64 + (tx << 2);
#pragma unroll
    for (int i = 0; i < 4; i++)
#pragma unroll
        for (int j = 0; j < 4; j++) {
            float v = acc[i][j] * alpha;
            if (bias) v += bias[c0 + j];
            if (act)  v = 0.5f * v * (1.f + erff(v * 0.70710678118654752f));
            if (res)  v += res[(size_t)(r0 + i) * N + c0 + j];
            C[(size_t)(r0 + i) * N + c0 + j] = v;
        }
}

// ---------------- tiled SGEMM NN: C = A @ B, B row-major [K,N] --------------
__global__ void gemm_nn(const float* __restrict__ A, const float* __restrict__ Bm,
                        float* __restrict__ C,
                        int M, int N, int K,
                        long long sA, long long sB, long long sC)
{
    __shared__ float As[16][64];
    __shared__ float Bs[16][64];
    int bz = blockIdx.z;
    A  += (size_t)bz * sA;
    Bm += (size_t)bz * sB;
    C  += (size_t)bz * sC;

    int tid = threadIdx.x;
    int lr = tid >> 2;
    int lc = (tid & 3) << 2;
    const float* Ap = A + (size_t)(blockIdx.y * 64 + lr) * K + lc;
    int kr = tid >> 4;          // 0..15 (k row of B tile)
    int nc = (tid & 15) << 2;   // 0..60
    const float* Bp = Bm + (size_t)kr * N + blockIdx.x * 64 + nc;
    int ty = tid >> 4, tx = tid & 15;
    float acc[4][4] = {};

    for (int k0 = 0; k0 < K; k0 += 16) {
        float4 a4 = *(const float4*)(Ap + k0);
        float4 b4 = *(const float4*)(Bp + (size_t)k0 * N);
        As[lc + 0][lr] = a4.x; As[lc + 1][lr] = a4.y;
        As[lc + 2][lr] = a4.z; As[lc + 3][lr] = a4.w;
        *(float4*)&Bs[kr][nc] = b4;
        __syncthreads();
#pragma unroll
        for (int k = 0; k < 16; k++) {
            float4 ra = *(const float4*)&As[k][ty << 2];
            float4 rb = *(const float4*)&Bs[k][tx << 2];
            float a[4] = {ra.x, ra.y, ra.z, ra.w};
            float b[4] = {rb.x, rb.y, rb.z, rb.w};
#pragma unroll
            for (int i = 0; i < 4; i++)
#pragma unroll
                for (int j = 0; j < 4; j++)
                    acc[i][j] += a[i] * b[j];
        }
        __syncthreads();
    }

    int r0 = blockIdx.y * 64 + (ty << 2);
    int c0 = blockIdx.x * 64 + (tx << 2);
#pragma unroll
    for (int i = 0; i < 4; i++)
#pragma unroll
        for (int j = 0; j < 4; j++)
            C[(size_t)(r0 + i) * N + c0 + j] = acc[i][j];
}

// ---------------- qkv split: [8192,3072] -> q/k/v in [B,H,N,D] --------------
__global__ void split_qkv(const float* __restrict__ qkv,
                          float* __restrict__ q, float* __restrict__ k,
                          float* __restrict__ v)
{
    size_t idx = (size_t)blockIdx.x * 256 + threadIdx.x; // 8192*3072 total
    int r = (int)(idx / 3072);
    int j = (int)(idx % 3072);
    int which = j >> 10;
    int c = j & 1023;
    int hh = c >> 6;
    int d  = c & 63;
    int b  = r >> 10;
    int n  = r & 1023;
    float val = qkv[idx];
    float* dst = (which == 0) ? q : (which == 1) ? k : v;
    dst[((size_t)(b * 16 + hh) * 1024 + n) * 64 + d] = val;
}

// ---------------- o reshape: [B,H,N,D] -> [B,N,C] ---------------------------
__global__ void reshape_o(const float* __restrict__ o, float* __restrict__ o2)
{
    size_t idx = (size_t)blockIdx.x * 256 + threadIdx.x; // 8*16*1024*64
    int bh = (int)(idx >> 16);        // /(1024*64)
    int r  = (int)(idx & 65535);
    int n  = r >> 6;
    int d  = r & 63;
    int b  = bh >> 4;
    int hh = bh & 15;
    o2[((size_t)(b * 1024 + n)) * 1024 + hh * 64 + d] = o[idx];
}

// ---------------- template bank: w[idx] = sum_t tpl[t][idx] * ct[t] ---------
__global__ void bank_kernel(const float* __restrict__ tpl,
                            const float* __restrict__ coef,
                            float* __restrict__ w, int total)
{
    int idx = blockIdx.x * 256 + threadIdx.x;
    if (idx >= total) return;
    float acc = 0.f;
#pragma unroll
    for (int t = 0; t < 16; t++) {
        float ct = 0.5f * (coef[t] + coef[16 + t]);
        acc += tpl[(size_t)t * total + idx] * ct;
    }
    w[idx] = acc;
}

// ---------------- launcher --------------------------------------------------
extern "C" void kernel_launch(void* const* d_in, const int* in_sizes, int n_in,
                              void* d_out, int out_size)
{
    const float* x      = (const float*)d_in[0];
    const float* ln1_g  = (const float*)d_in[1];
    const float* ln1_b  = (const float*)d_in[2];
    const float* qkv_w  = (const float*)d_in[3];
    const float* proj_w = (const float*)d_in[4];
    const float* proj_b = (const float*)d_in[5];
    const float* ln2_g  = (const float*)d_in[6];
    const float* ln2_b  = (const float*)d_in[7];
    const float* tpl1   = (const float*)d_in[8];
    const float* cf1    = (const float*)d_in[9];
    const float* bias1  = (const float*)d_in[10];
    const float* tpl2   = (const float*)d_in[11];
    const float* cf2    = (const float*)d_in[12];
    const float* bias2  = (const float*)d_in[13];
    float* out = (float*)d_out;

    float *ph, *pqkv, *pq, *pk, *pv, *ps, *po, *po2, *py, *pw1, *pw2;
    cudaGetSymbolAddress((void**)&ph,   g_h);
    cudaGetSymbolAddress((void**)&pqkv, g_qkv);
    cudaGetSymbolAddress((void**)&pq,   g_q);
    cudaGetSymbolAddress((void**)&pk,   g_k);
    cudaGetSymbolAddress((void**)&pv,   g_v);
    cudaGetSymbolAddress((void**)&ps,   g_s);
    cudaGetSymbolAddress((void**)&po,   g_o);
    cudaGetSymbolAddress((void**)&po2,  g_o2);
    cudaGetSymbolAddress((void**)&py,   g_y);
    cudaGetSymbolAddress((void**)&pw1,  g_w1);
    cudaGetSymbolAddress((void**)&pw2,  g_w2);

    // 1. LN1(x) -> h
    ln_kernel<<<8192, 256>>>(x, ln1_g, ln1_b, ph);

    // 2. qkv = h @ qkv_w^T  [8192,3072]
    gemm_nt<<<dim3(48, 128, 1), 256>>>(ph, qkv_w, pqkv, nullptr, nullptr,
                                       8192, 3072, 1024, 0, 0, 0, 1.f, 0);

    // 3. split into q/k/v [B,H,N,D]
    split_qkv<<<98304, 256>>>(pqkv, pq, pk, pv);

    // 4. scores = scale * Q @ K^T  per (b,h), batch=128
    gemm_nt<<<dim3(16, 16, 128), 256>>>(pq, pk, ps, nullptr, nullptr,
                                        1024, 1024, 64,
                                        65536LL, 65536LL, 1048576LL, 0.125f, 0);

    // 5. softmax over last dim (131072 rows)
    softmax_kernel<<<131072, 256>>>(ps);

    // 6. o = S @ V  per (b,h)
    gemm_nn<<<dim3(1, 16, 128), 256>>>(ps, pv, po,
                                       1024, 64, 1024,
                                       1048576LL, 65536LL, 65536LL);

    // 7. reshape o -> [B,N,C]
    reshape_o<<<32768, 256>>>(po, po2);

    // 8. x2 = x + o2 @ proj_w^T + proj_b   (written into d_out)
    gemm_nt<<<dim3(16, 128, 1), 256>>>(po2, proj_w, out, x, proj_b,
                                       8192, 1024, 1024, 0, 0, 0, 1.f, 0);

    // 9. LN2(x2) -> h (reuse)
    ln_kernel<<<8192, 256>>>(out, ln2_g, ln2_b, ph);

    // 10/11. template banks -> w1 [4096,1024], w2 [1024,4096]
    bank_kernel<<<16384, 256>>>(tpl1, cf1, pw1, HID * CC);
    bank_kernel<<<16384, 256>>>(tpl2, cf2, pw2, CC * HID);

    // 12. y = gelu(h @ w1^T + bias1)  [8192,4096]
    gemm_nt<<<dim3(64, 128, 1), 256>>>(ph, pw1, py, nullptr, bias1,
                                       8192, 4096, 1024, 0, 0, 0, 1.f, 1);

    // 13. out = x2 + y @ w2^T + bias2
    gemm_nt<<<dim3(16, 128, 1), 256>>>(py, pw2, out, out, bias2,
                                       8192, 1024, 4096, 0, 0, 0, 1.f, 0);
}

// round 4
// speedup vs baseline: 2.3533x; 2.3533x over previous
#include <cuda_runtime.h>
#include <cuda_bf16.h>
#include <cstdint>
#include <math.h>

#define MROWS 8192

// ---------------- scratch (static device globals) ---------------------------
__device__ float g_qkv[(size_t)MROWS * 3072];               // qkv out fp32
__device__ float g_s  [(size_t)128 * 1024 * 1024];          // scores fp32
__device__ __nv_bfloat16 g_h3    [(size_t)MROWS * 3072];    // LN out, split
__device__ __nv_bfloat16 g_wqkv3 [(size_t)3072 * 3072];
__device__ __nv_bfloat16 g_wproj3[(size_t)1024 * 3072];
__device__ __nv_bfloat16 g_w13   [(size_t)4096 * 3072];
__device__ __nv_bfloat16 g_w23   [(size_t)1024 * 12288];
__device__ __nv_bfloat16 g_q3    [(size_t)128 * 1024 * 192];
__device__ __nv_bfloat16 g_k3    [(size_t)128 * 1024 * 192];
__device__ __nv_bfloat16 g_vT3   [(size_t)128 * 64 * 3072];
__device__ __nv_bfloat16 g_s3    [(size_t)128 * 1024 * 3072];
__device__ __nv_bfloat16 g_o23   [(size_t)MROWS * 3072];
__device__ __nv_bfloat16 g_y3    [(size_t)MROWS * 12288];

// ---------------- helpers ----------------------------------------------------
__device__ __forceinline__ uint32_t smem_u32(const void* p) {
    uint32_t a;
    asm("{ .reg .u64 t; cvta.to.shared.u64 t, %1; cvt.u32.u64 %0, t; }" : "=r"(a) : "l"(p));
    return a;
}
__device__ __forceinline__ void cp16(uint32_t saddr, const void* g) {
    asm volatile("cp.async.cg.shared.global [%0], [%1], 16;" :: "r"(saddr), "l"(g));
}
#define CP_COMMIT() asm volatile("cp.async.commit_group;" ::: "memory")
#define CP_WAIT1()  asm volatile("cp.async.wait_group 1;" ::: "memory")

__device__ __forceinline__ void ldsm4(uint32_t* r, uint32_t a) {
    asm volatile("ldmatrix.sync.aligned.m8n8.x4.shared.b16 {%0,%1,%2,%3}, [%4];"
                 : "=r"(r[0]), "=r"(r[1]), "=r"(r[2]), "=r"(r[3]) : "r"(a));
}
__device__ __forceinline__ void mma16816(float* c, const uint32_t* a, uint32_t b0, uint32_t b1) {
    asm volatile("mma.sync.aligned.m16n8k16.row.col.f32.bf16.bf16.f32 "
                 "{%0,%1,%2,%3}, {%4,%5,%6,%7}, {%8,%9}, {%0,%1,%2,%3};"
                 : "+f"(c[0]), "+f"(c[1]), "+f"(c[2]), "+f"(c[3])
                 : "r"(a[0]), "r"(a[1]), "r"(a[2]), "r"(a[3]), "r"(b0), "r"(b1));
}
__device__ __forceinline__ void split_bf16(float v, __nv_bfloat16& hi, __nv_bfloat16& lo) {
    hi = __float2bfloat16(v);
    lo = __float2bfloat16(v - __bfloat162float(hi));
}

// ---------------- HMMA split GEMM: C = alpha*(A3 @ B3^T) ---------------------
// A3 [M,K3], B3 [N,K3] row-major bf16 (K-major both). CTA tile 128 x NTILE,
// BK=32, 3-stage cp.async ring, 8 warps (4x2), m16n8k16 HMMA.
// Epilogue: fp32 (+bias,+gelu,+res) OR split-bf16 x3 (A-side layout).
template<int NTILE>
__global__ void __launch_bounds__(256)
mm_gemm(const __nv_bfloat16* __restrict__ A, const __nv_bfloat16* __restrict__ B,
        int K3, long long sAz, long long sBz,
        float* __restrict__ C, __nv_bfloat16* __restrict__ O3,
        long long ldc, int Ksp,
        int cdiv, long long sCo, long long sCi,
        const float* __restrict__ bias, const float* __restrict__ res,
        float alpha, int gelu_f)
{
    extern __shared__ __align__(1024) char smem[];
    const int STAGE = 8192 + NTILE * 64;       // A:128x32x2 + B:NTILEx32x2
    const int WN   = NTILE / 2;                // warp n-width
    const int NBX4 = WN / 16;                  // B ldmatrix.x4 per k16
    const int NB8  = WN / 8;                   // n8 frags per warp
    const int NB_LD = (NTILE * 4) / 256;       // B cp.async chunks per thread

    int tid = threadIdx.x;
    int wid = tid >> 5;
    int l   = tid & 31;
    int mw  = wid & 3;
    int nw  = wid >> 2;

    int bn = blockIdx.x, bm = blockIdx.y, z = blockIdx.z;
    A += (size_t)z * sAz + (size_t)bm * 128 * K3;
    B += (size_t)z * sBz + (size_t)bn * NTILE * K3;

    uint32_t sbase = smem_u32(smem);

    // cp.async per-thread offsets
    uint32_t a_soff[2]; size_t a_goff[2];
#pragma unroll
    for (int i = 0; i < 2; i++) {
        int id = tid + 256 * i;
        int row = id >> 2, c = id & 3;
        a_soff[i] = (uint32_t)(row * 64 + ((c ^ (row & 3)) << 4));
        a_goff[i] = (size_t)row * K3 + c * 8;
    }
    uint32_t b_soff[NB_LD]; size_t b_goff[NB_LD];
#pragma unroll
    for (int i = 0; i < NB_LD; i++) {
        int id = tid + 256 * i;
        int row = id >> 2, c = id & 3;
        b_soff[i] = (uint32_t)(8192 + row * 64 + ((c ^ (row & 3)) << 4));
        b_goff[i] = (size_t)row * K3 + c * 8;
    }
    // ldmatrix per-lane offsets
    uint32_t lma[2][2], lmb[NBX4][2];
#pragma unroll
    for (int i = 0; i < 2; i++)
#pragma unroll
        for (int kh = 0; kh < 2; kh++) {
            int row = mw * 32 + i * 16 + (l & 15);
            int c = (l >> 4) + kh * 2;
            lma[i][kh] = (uint32_t)(row * 64 + ((c ^ (row & 3)) << 4));
        }
#pragma unroll
    for (int j2 = 0; j2 < NBX4; j2++)
#pragma unroll
        for (int kh = 0; kh < 2; kh++) {
            int row = nw * WN + j2 * 16 + (l & 15);
            int c = (l >> 4) + kh * 2;
            lmb[j2][kh] = (uint32_t)(8192 + row * 64 + ((c ^ (row & 3)) << 4));
        }

    float acc[2][NB8][4];
#pragma unroll
    for (int i = 0; i < 2; i++)
#pragma unroll
        for (int j = 0; j < NB8; j++)
#pragma unroll
            for (int k = 0; k < 4; k++) acc[i][j][k] = 0.f;

    int nk = K3 >> 5;   // BK=32

    auto issue = [&](int ks) {
        if (ks < nk) {
            uint32_t st = sbase + (ks % 3) * STAGE;
            const __nv_bfloat16* Ag = A + (size_t)ks * 32;
            const __nv_bfloat16* Bg = B + (size_t)ks * 32;
#pragma unroll
            for (int i = 0; i < 2; i++) cp16(st + a_soff[i], Ag + a_goff[i]);
#pragma unroll
            for (int i = 0; i < NB_LD; i++) cp16(st + b_soff[i], Bg + b_goff[i]);
        }
        CP_COMMIT();
    };

    issue(0); issue(1);

    for (int ks = 0; ks < nk; ks++) {
        CP_WAIT1();
        __syncthreads();
        issue(ks + 2);
        uint32_t st = sbase + (ks % 3) * STAGE;
#pragma unroll
        for (int kh = 0; kh < 2; kh++) {
            uint32_t afr[2][4];
#pragma unroll
            for (int i = 0; i < 2; i++) ldsm4(afr[i], st + lma[i][kh]);
            uint32_t bfr[NBX4][4];
#pragma unroll
            for (int j2 = 0; j2 < NBX4; j2++) ldsm4(bfr[j2], st + lmb[j2][kh]);
#pragma unroll
            for (int i = 0; i < 2; i++)
#pragma unroll
                for (int j = 0; j < NB8; j++) {
                    int j2 = j >> 1, hb = j & 1;
                    mma16816(acc[i][j], afr[i], bfr[j2][hb], bfr[j2][hb + 2]);
                }
        }
    }
    __syncthreads();

    // ---- epilogue: regs -> SMEM (transpose) -> coalesced GMEM --------------
    const int pitch = NTILE + 4;
    float* smf = (float*)smem;
#pragma unroll
    for (int i = 0; i < 2; i++)
#pragma unroll
        for (int j = 0; j < NB8; j++) {
            int r = mw * 32 + i * 16 + (l >> 2);
            int c = nw * WN + j * 8 + (l & 3) * 2;
            *(float2*)&smf[r * pitch + c]       = make_float2(acc[i][j][0], acc[i][j][1]);
            *(float2*)&smf[(r + 8) * pitch + c] = make_float2(acc[i][j][2], acc[i][j][3]);
        }
    __syncthreads();

    long long zo = (long long)(z / cdiv) * sCo + (long long)(z % cdiv) * sCi;
    int m0 = bm * 128;
    const int TPR = NTILE / 8;        // threads per row
    const int RPP = 256 / TPR;        // rows per pass
#pragma unroll
    for (int p = 0; p < 128 / RPP; p++) {
        int row = p * RPP + tid / TPR;
        int c8 = (tid % TPR) * 8;
        float vals[8];
#pragma unroll
        for (int i = 0; i < 8; i++) vals[i] = smf[row * pitch + c8 + i];
#pragma unroll
        for (int i = 0; i < 8; i++) {
            float v = vals[i] * alpha;
            if (bias) v += bias[bn * NTILE + c8 + i];
            if (gelu_f) v = 0.5f * v * (1.f + erff(v * 0.70710678118654752f));
            vals[i] = v;
        }
        size_t ci = (size_t)zo + (size_t)(m0 + row) * ldc + bn * NTILE + c8;
        if (O3) {
            __align__(16) __nv_bfloat16 hb[8];
            __align__(16) __nv_bfloat16 lb[8];
#pragma unroll
            for (int i = 0; i < 8; i++) split_bf16(vals[i], hb[i], lb[i]);
            *(uint4*)(O3 + ci)                   = *(uint4*)hb;
            *(uint4*)(O3 + ci + (size_t)Ksp)     = *(uint4*)hb;
            *(uint4*)(O3 + ci + 2 * (size_t)Ksp) = *(uint4*)lb;
        } else {
            if (res) {
                float4 r1 = *(const float4*)(res + ci);
                float4 r2 = *(const float4*)(res + ci + 4);
                vals[0] += r1.x; vals[1] += r1.y; vals[2] += r1.z; vals[3] += r1.w;
                vals[4] += r2.x; vals[5] += r2.y; vals[6] += r2.z; vals[7] += r2.w;
            }
            *(float4*)(C + ci)     = make_float4(vals[0], vals[1], vals[2], vals[3]);
            *(float4*)(C + ci + 4) = make_float4(vals[4], vals[5], vals[6], vals[7]);
        }
    }
}

// ---------------- LayerNorm -> split bf16 [hi|hi|lo], K=1024 ----------------
__global__ void ln_split(const float* __restrict__ x, const float* __restrict__ g,
                         const float* __restrict__ b, __nv_bfloat16* __restrict__ out3)
{
    __shared__ float sh1[8], sh2[8];
    int row = blockIdx.x;
    int tid = threadIdx.x;
    const float* p = x + (size_t)row * 1024;
    float v[4];
    float s = 0.f, sq = 0.f;
#pragma unroll
    for (int j = 0; j < 4; j++) {
        v[j] = p[tid + j * 256];
        s += v[j]; sq += v[j] * v[j];
    }
#pragma unroll
    for (int o = 16; o > 0; o >>= 1) {
        s  += __shfl_xor_sync(0xffffffffu, s,  o);
        sq += __shfl_xor_sync(0xffffffffu, sq, o);
    }
    if ((tid & 31) == 0) { sh1[tid >> 5] = s; sh2[tid >> 5] = sq; }
    __syncthreads();
    if (tid == 0) {
        float a = 0.f, c = 0.f;
        for (int i = 0; i < 8; i++) { a += sh1[i]; c += sh2[i]; }
        sh1[0] = a; sh2[0] = c;
    }
    __syncthreads();
    float mean = sh1[0] * (1.f / 1024.f);
    float var  = sh2[0] * (1.f / 1024.f) - mean * mean;
    float rstd = rsqrtf(var + 1e-5f);
    __nv_bfloat16* q = out3 + (size_t)row * 3072;
#pragma unroll
    for (int j = 0; j < 4; j++) {
        int i = tid + j * 256;
        float val = (v[j] - mean) * rstd * g[i] + b[i];
        __nv_bfloat16 hi, lo; split_bf16(val, hi, lo);
        q[i] = hi; q[1024 + i] = hi; q[2048 + i] = lo;
    }
}

// ---------------- softmax -> split bf16 [hi|hi|lo] (A-side) -----------------
__global__ void softmax_split(const float* __restrict__ S, __nv_bfloat16* __restrict__ S3)
{
    __shared__ float sh[8];
    size_t row = blockIdx.x;
    const float* p = S + row * 1024;
    int tid = threadIdx.x;
    float v[4];
    float m = -1e30f;
#pragma unroll
    for (int j = 0; j < 4; j++) { v[j] = p[tid + j * 256]; m = fmaxf(m, v[j]); }
#pragma unroll
    for (int o = 16; o > 0; o >>= 1)
        m = fmaxf(m, __shfl_xor_sync(0xffffffffu, m, o));
    if ((tid & 31) == 0) sh[tid >> 5] = m;
    __syncthreads();
    if (tid == 0) {
        float a = sh[0];
        for (int i = 1; i < 8; i++) a = fmaxf(a, sh[i]);
        sh[0] = a;
    }
    __syncthreads();
    m = sh[0];
    __syncthreads();
    float s = 0.f;
#pragma unroll
    for (int j = 0; j < 4; j++) { v[j] = expf(v[j] - m); s += v[j]; }
#pragma unroll
    for (int o = 16; o > 0; o >>= 1)
        s += __shfl_xor_sync(0xffffffffu, s, o);
    if ((tid & 31) == 0) sh[tid >> 5] = s;
    __syncthreads();
    if (tid == 0) {
        float a = 0.f;
        for (int i = 0; i < 8; i++) a += sh[i];
        sh[0] = a;
    }
    __syncthreads();
    float inv = 1.f / sh[0];
    __nv_bfloat16* q = S3 + row * 3072;
#pragma unroll
    for (int j = 0; j < 4; j++) {
        int i = tid + j * 256;
        __nv_bfloat16 hi, lo; split_bf16(v[j] * inv, hi, lo);
        q[i] = hi; q[1024 + i] = hi; q[2048 + i] = lo;
    }
}

// ---------------- weight fp32 [R,K] -> split bf16 [hi|lo|hi] (B-side) -------
__global__ void conv_w3(const float* __restrict__ Wm, __nv_bfloat16* __restrict__ W3,
                        int K, int total)
{
    int idx = blockIdx.x * 256 + threadIdx.x;
    if (idx >= total) return;
    int r = idx / K, k = idx - r * K;
    __nv_bfloat16 hi, lo; split_bf16(Wm[idx], hi, lo);
    size_t base = (size_t)r * 3 * K + k;
    W3[base] = hi; W3[base + K] = lo; W3[base + 2 * K] = hi;
}

// ---------------- qkv -> q3 (A-side), k3 (B-side) ---------------------------
__global__ void qk_split(const float* __restrict__ qkv,
                         __nv_bfloat16* __restrict__ q3, __nv_bfloat16* __restrict__ k3)
{
    size_t idx = (size_t)blockIdx.x * 256 + threadIdx.x;   // 8192*2048
    int r = (int)(idx >> 11);
    int j = (int)(idx & 2047);
    int isK = j >> 10;
    int c = j & 1023;
    int h = c >> 6, d = c & 63;
    int b = r >> 10, n = r & 1023;
    float val = qkv[(size_t)r * 3072 + j];
    __nv_bfloat16 hi, lo; split_bf16(val, hi, lo);
    size_t base = ((size_t)(b * 16 + h) * 1024 + n) * 192;
    if (isK == 0) { q3[base + d] = hi; q3[base + 64 + d] = hi; q3[base + 128 + d] = lo; }
    else          { k3[base + d] = hi; k3[base + 64 + d] = lo; k3[base + 128 + d] = hi; }
}

// ---------------- v -> vT3 transposed split (B-side) [hi|lo|hi] -------------
__global__ void v_split(const float* __restrict__ qkv, __nv_bfloat16* __restrict__ vT3)
{
    size_t idx = (size_t)blockIdx.x * 256 + threadIdx.x;   // 128*64*1024
    int bh = (int)(idx >> 16);
    int rest = (int)(idx & 65535);
    int d = rest >> 10, n = rest & 1023;
    int b = bh >> 4, h = bh & 15;
    float val = qkv[((size_t)(b * 1024 + n)) * 3072 + 2048 + h * 64 + d];
    __nv_bfloat16 hi, lo; split_bf16(val, hi, lo);
    size_t base = ((size_t)bh * 64 + d) * 3072;
    vT3[base + n] = hi; vT3[base + 1024 + n] = lo; vT3[base + 2048 + n] = hi;
}

// ---------------- template banks -> split bf16 (B-side) ---------------------
__global__ void bank_split(const float* __restrict__ tpl, const float* __restrict__ coef,
                           __nv_bfloat16* __restrict__ W3, int K, int total)
{
    int idx = blockIdx.x * 256 + threadIdx.x;
    if (idx >= total) return;
    float acc = 0.f;
#pragma unroll
    for (int t = 0; t < 16; t++) {
        float ct = 0.5f * (coef[t] + coef[16 + t]);
        acc += tpl[(size_t)t * total + idx] * ct;
    }
    int r = idx / K, k = idx - r * K;
    __nv_bfloat16 hi, lo; split_bf16(acc, hi, lo);
    size_t base = (size_t)r * 3 * K + k;
    W3[base] = hi; W3[base + K] = lo; W3[base + 2 * K] = hi;
}

// ---------------- launcher --------------------------------------------------
extern "C" void kernel_launch(void* const* d_in, const int* in_sizes, int n_in,
                              void* d_out, int out_size)
{
    const float* x      = (const float*)d_in[0];
    const float* ln1_g  = (const float*)d_in[1];
    const float* ln1_b  = (const float*)d_in[2];
    const float* qkv_w  = (const float*)d_in[3];
    const float* proj_w = (const float*)d_in[4];
    const float* proj_b = (const float*)d_in[5];
    const float* ln2_g  = (const float*)d_in[6];
    const float* ln2_b  = (const float*)d_in[7];
    const float* tpl1   = (const float*)d_in[8];
    const float* cf1    = (const float*)d_in[9];
    const float* bias1  = (const float*)d_in[10];
    const float* tpl2   = (const float*)d_in[11];
    const float* cf2    = (const float*)d_in[12];
    const float* bias2  = (const float*)d_in[13];
    float* out = (float*)d_out;

    float *pqkv, *ps;
    __nv_bfloat16 *ph3, *pwqkv3, *pwproj3, *pw13, *pw23, *pq3, *pk3, *pvT3, *ps3, *po23, *py3;
    cudaGetSymbolAddress((void**)&pqkv,   g_qkv);
    cudaGetSymbolAddress((void**)&ps,     g_s);
    cudaGetSymbolAddress((void**)&ph3,    g_h3);
    cudaGetSymbolAddress((void**)&pwqkv3, g_wqkv3);
    cudaGetSymbolAddress((void**)&pwproj3,g_wproj3);
    cudaGetSymbolAddress((void**)&pw13,   g_w13);
    cudaGetSymbolAddress((void**)&pw23,   g_w23);
    cudaGetSymbolAddress((void**)&pq3,    g_q3);
    cudaGetSymbolAddress((void**)&pk3,    g_k3);
    cudaGetSymbolAddress((void**)&pvT3,   g_vT3);
    cudaGetSymbolAddress((void**)&ps3,    g_s3);
    cudaGetSymbolAddress((void**)&po23,   g_o23);
    cudaGetSymbolAddress((void**)&py3,    g_y3);

    // dyn smem: max(3-stage ring, epilogue transpose buffer)
    const int SM128 = 128 * 132 * 4;                 // 67584 > 49152
    const int SM64  = 3 * (8192 + 64 * 64);          // 36864 > 34816
    cudaFuncSetAttribute(mm_gemm<128>, cudaFuncAttributeMaxDynamicSharedMemorySize, SM128);
    cudaFuncSetAttribute(mm_gemm<64>,  cudaFuncAttributeMaxDynamicSharedMemorySize, SM64);

    // 1. LN1(x) -> h3 (split)
    ln_split<<<8192, 256>>>(x, ln1_g, ln1_b, ph3);
    // 2. weight conversions + banks
    conv_w3<<<(3072 * 1024 + 255) / 256, 256>>>(qkv_w, pwqkv3, 1024, 3072 * 1024);
    conv_w3<<<(1024 * 1024 + 255) / 256, 256>>>(proj_w, pwproj3, 1024, 1024 * 1024);
    bank_split<<<(4096 * 1024 + 255) / 256, 256>>>(tpl1, cf1, pw13, 1024, 4096 * 1024);
    bank_split<<<(1024 * 4096 + 255) / 256, 256>>>(tpl2, cf2, pw23, 4096, 1024 * 4096);

    // 3. qkv = h3 @ wqkv3^T  [8192,3072] fp32
    mm_gemm<128><<<dim3(24, 64, 1), 256, SM128>>>(
        ph3, pwqkv3, 3072, 0, 0,
        pqkv, nullptr, 3072, 0, 1, 0, 0, nullptr, nullptr, 1.f, 0);

    // 4. split qkv -> q3/k3/vT3
    qk_split<<<(int)(((size_t)8192 * 2048) / 256), 256>>>(pqkv, pq3, pk3);
    v_split<<<(int)(((size_t)128 * 64 * 1024) / 256), 256>>>(pqkv, pvT3);

    // 5. S = 0.125 * q3 @ k3^T   batch 128, [1024,1024] fp32
    mm_gemm<128><<<dim3(8, 8, 128), 256, SM128>>>(
        pq3, pk3, 192, 196608LL, 196608LL,
        ps, nullptr, 1024, 0, 1, 1048576LL, 0, nullptr, nullptr, 0.125f, 0);

    // 6. softmax -> s3 (split)
    softmax_split<<<131072, 256>>>(ps, ps3);

    // 7. o2_3(split) = s3 @ vT3^T  batch 128, N=64, scattered into [B,N,C]
    mm_gemm<64><<<dim3(1, 8, 128), 256, SM64>>>(
        ps3, pvT3, 3072, (long long)1024 * 3072, (long long)64 * 3072,
        nullptr, po23, 3072, 1024, 16, (long long)1024 * 3072, 64,
        nullptr, nullptr, 1.f, 0);

    // 8. out = x + o2_3 @ wproj3^T + proj_b
    mm_gemm<128><<<dim3(8, 64, 1), 256, SM128>>>(
        po23, pwproj3, 3072, 0, 0,
        out, nullptr, 1024, 0, 1, 0, 0, proj_b, x, 1.f, 0);

    // 9. LN2(out) -> h3 (split)
    ln_split<<<8192, 256>>>(out, ln2_g, ln2_b, ph3);

    // 10. y3(split) = gelu(h3 @ w13^T + bias1)  [8192,4096]
    mm_gemm<128><<<dim3(32, 64, 1), 256, SM128>>>(
        ph3, pw13, 3072, 0, 0,
        nullptr, py3, 12288, 4096, 1, 0, 0, bias1, nullptr, 1.f, 1);

    // 11. out = out + y3 @ w23^T + bias2
    mm_gemm<128><<<dim3(8, 64, 1), 256, SM128>>>(
        py3, pw23, 12288, 0, 0,
        out, nullptr, 1024, 0, 1, 0, 0, bias2, out, 1.f, 0);
}

// round 5
// speedup vs baseline: 2.6204x; 1.1135x over previous
#include <cuda_runtime.h>
#include <cuda_bf16.h>
#include <cstdint>
#include <math.h>

#define MROWS 8192

// ---------------- scratch (static device globals) ---------------------------
__device__ float g_qkv[(size_t)MROWS * 3072];               // qkv out fp32
__device__ __nv_bfloat16 g_h3    [(size_t)MROWS * 3072];    // LN out, split
__device__ __nv_bfloat16 g_wqkv3 [(size_t)3072 * 3072];
__device__ __nv_bfloat16 g_wproj3[(size_t)1024 * 3072];
__device__ __nv_bfloat16 g_w13   [(size_t)4096 * 3072];
__device__ __nv_bfloat16 g_w23   [(size_t)1024 * 12288];
__device__ __nv_bfloat16 g_q3    [(size_t)128 * 1024 * 192];
__device__ __nv_bfloat16 g_k3    [(size_t)128 * 1024 * 192];
__device__ __nv_bfloat16 g_vT3   [(size_t)128 * 64 * 3072];
__device__ __nv_bfloat16 g_o23   [(size_t)MROWS * 3072];
__device__ __nv_bfloat16 g_y3    [(size_t)MROWS * 12288];

// ---------------- helpers ----------------------------------------------------
__device__ __forceinline__ uint32_t smem_u32(const void* p) {
    uint32_t a;
    asm("{ .reg .u64 t; cvta.to.shared.u64 t, %1; cvt.u32.u64 %0, t; }" : "=r"(a) : "l"(p));
    return a;
}
__device__ __forceinline__ void cp16(uint32_t saddr, const void* g) {
    asm volatile("cp.async.cg.shared.global [%0], [%1], 16;" :: "r"(saddr), "l"(g));
}
#define CP_COMMIT() asm volatile("cp.async.commit_group;" ::: "memory")
#define CP_WAIT1()  asm volatile("cp.async.wait_group 1;" ::: "memory")
#define CP_WAIT0()  asm volatile("cp.async.wait_group 0;" ::: "memory")

__device__ __forceinline__ void ldsm4(uint32_t* r, uint32_t a) {
    asm volatile("ldmatrix.sync.aligned.m8n8.x4.shared.b16 {%0,%1,%2,%3}, [%4];"
                 : "=r"(r[0]), "=r"(r[1]), "=r"(r[2]), "=r"(r[3]) : "r"(a));
}
__device__ __forceinline__ void mma16816(float* c, const uint32_t* a, uint32_t b0, uint32_t b1) {
    asm volatile("mma.sync.aligned.m16n8k16.row.col.f32.bf16.bf16.f32 "
                 "{%0,%1,%2,%3}, {%4,%5,%6,%7}, {%8,%9}, {%0,%1,%2,%3};"
                 : "+f"(c[0]), "+f"(c[1]), "+f"(c[2]), "+f"(c[3])
                 : "r"(a[0]), "r"(a[1]), "r"(a[2]), "r"(a[3]), "r"(b0), "r"(b1));
}
__device__ __forceinline__ void split_bf16(float v, __nv_bfloat16& hi, __nv_bfloat16& lo) {
    hi = __float2bfloat16(v);
    lo = __float2bfloat16(v - __bfloat162float(hi));
}
__device__ __forceinline__ uint32_t pack_bf(float a, float b) {
    __nv_bfloat16 x = __float2bfloat16(a), y = __float2bfloat16(b);
    return ((uint32_t)*(uint16_t*)&y << 16) | *(uint16_t*)&x;
}

// ---------------- HMMA split GEMM: C = alpha*(A3 @ B3^T) ---------------------
template<int NTILE>
__global__ void __launch_bounds__(256)
mm_gemm(const __nv_bfloat16* __restrict__ A, const __nv_bfloat16* __restrict__ B,
        int K3, long long sAz, long long sBz,
        float* __restrict__ C, __nv_bfloat16* __restrict__ O3,
        long long ldc, int Ksp,
        int cdiv, long long sCo, long long sCi,
        const float* __restrict__ bias, const float* __restrict__ res,
        float alpha, int gelu_f)
{
    extern __shared__ __align__(1024) char smem[];
    const int STAGE = 8192 + NTILE * 64;
    const int WN   = NTILE / 2;
    const int NBX4 = WN / 16;
    const int NB8  = WN / 8;
    const int NB_LD = (NTILE * 4) / 256;

    int tid = threadIdx.x;
    int wid = tid >> 5;
    int l   = tid & 31;
    int mw  = wid & 3;
    int nw  = wid >> 2;

    int bn = blockIdx.x, bm = blockIdx.y, z = blockIdx.z;
    A += (size_t)z * sAz + (size_t)bm * 128 * K3;
    B += (size_t)z * sBz + (size_t)bn * NTILE * K3;

    uint32_t sbase = smem_u32(smem);

    uint32_t a_soff[2]; size_t a_goff[2];
#pragma unroll
    for (int i = 0; i < 2; i++) {
        int id = tid + 256 * i;
        int row = id >> 2, c = id & 3;
        a_soff[i] = (uint32_t)(row * 64 + ((c ^ (row & 3)) << 4));
        a_goff[i] = (size_t)row * K3 + c * 8;
    }
    uint32_t b_soff[NB_LD]; size_t b_goff[NB_LD];
#pragma unroll
    for (int i = 0; i < NB_LD; i++) {
        int id = tid + 256 * i;
        int row = id >> 2, c = id & 3;
        b_soff[i] = (uint32_t)(8192 + row * 64 + ((c ^ (row & 3)) << 4));
        b_goff[i] = (size_t)row * K3 + c * 8;
    }
    uint32_t lma[2][2], lmb[NBX4][2];
#pragma unroll
    for (int i = 0; i < 2; i++)
#pragma unroll
        for (int kh = 0; kh < 2; kh++) {
            int row = mw * 32 + i * 16 + (l & 15);
            int c = (l >> 4) + kh * 2;
            lma[i][kh] = (uint32_t)(row * 64 + ((c ^ (row & 3)) << 4));
        }
#pragma unroll
    for (int j2 = 0; j2 < NBX4; j2++)
#pragma unroll
        for (int kh = 0; kh < 2; kh++) {
            int row = nw * WN + j2 * 16 + (l & 15);
            int c = (l >> 4) + kh * 2;
            lmb[j2][kh] = (uint32_t)(8192 + row * 64 + ((c ^ (row & 3)) << 4));
        }

    float acc[2][NB8][4];
#pragma unroll
    for (int i = 0; i < 2; i++)
#pragma unroll
        for (int j = 0; j < NB8; j++)
#pragma unroll
            for (int k = 0; k < 4; k++) acc[i][j][k] = 0.f;

    int nk = K3 >> 5;

    auto issue = [&](int ks) {
        if (ks < nk) {
            uint32_t st = sbase + (ks % 3) * STAGE;
            const __nv_bfloat16* Ag = A + (size_t)ks * 32;
            const __nv_bfloat16* Bg = B + (size_t)ks * 32;
#pragma unroll
            for (int i = 0; i < 2; i++) cp16(st + a_soff[i], Ag + a_goff[i]);
#pragma unroll
            for (int i = 0; i < NB_LD; i++) cp16(st + b_soff[i], Bg + b_goff[i]);
        }
        CP_COMMIT();
    };

    issue(0); issue(1);

    for (int ks = 0; ks < nk; ks++) {
        CP_WAIT1();
        __syncthreads();
        issue(ks + 2);
        uint32_t st = sbase + (ks % 3) * STAGE;
#pragma unroll
        for (int kh = 0; kh < 2; kh++) {
            uint32_t afr[2][4];
#pragma unroll
            for (int i = 0; i < 2; i++) ldsm4(afr[i], st + lma[i][kh]);
            uint32_t bfr[NBX4][4];
#pragma unroll
            for (int j2 = 0; j2 < NBX4; j2++) ldsm4(bfr[j2], st + lmb[j2][kh]);
#pragma unroll
            for (int i = 0; i < 2; i++)
#pragma unroll
                for (int j = 0; j < NB8; j++) {
                    int j2 = j >> 1, hb = j & 1;
                    mma16816(acc[i][j], afr[i], bfr[j2][hb], bfr[j2][hb + 2]);
                }
        }
    }
    __syncthreads();

    const int pitch = NTILE + 4;
    float* smf = (float*)smem;
#pragma unroll
    for (int i = 0; i < 2; i++)
#pragma unroll
        for (int j = 0; j < NB8; j++) {
            int r = mw * 32 + i * 16 + (l >> 2);
            int c = nw * WN + j * 8 + (l & 3) * 2;
            *(float2*)&smf[r * pitch + c]       = make_float2(acc[i][j][0], acc[i][j][1]);
            *(float2*)&smf[(r + 8) * pitch + c] = make_float2(acc[i][j][2], acc[i][j][3]);
        }
    __syncthreads();

    long long zo = (long long)(z / cdiv) * sCo + (long long)(z % cdiv) * sCi;
    int m0 = bm * 128;
    const int TPR = NTILE / 8;
    const int RPP = 256 / TPR;
#pragma unroll
    for (int p = 0; p < 128 / RPP; p++) {
        int row = p * RPP + tid / TPR;
        int c8 = (tid % TPR) * 8;
        float vals[8];
#pragma unroll
        for (int i = 0; i < 8; i++) vals[i] = smf[row * pitch + c8 + i];
#pragma unroll
        for (int i = 0; i < 8; i++) {
            float v = vals[i] * alpha;
            if (bias) v += bias[bn * NTILE + c8 + i];
            if (gelu_f) v = 0.5f * v * (1.f + erff(v * 0.70710678118654752f));
            vals[i] = v;
        }
        size_t ci = (size_t)zo + (size_t)(m0 + row) * ldc + bn * NTILE + c8;
        if (O3) {
            __align__(16) __nv_bfloat16 hb[8];
            __align__(16) __nv_bfloat16 lb[8];
#pragma unroll
            for (int i = 0; i < 8; i++) split_bf16(vals[i], hb[i], lb[i]);
            *(uint4*)(O3 + ci)                   = *(uint4*)hb;
            *(uint4*)(O3 + ci + (size_t)Ksp)     = *(uint4*)hb;
            *(uint4*)(O3 + ci + 2 * (size_t)Ksp) = *(uint4*)lb;
        } else {
            if (res) {
                float4 r1 = *(const float4*)(res + ci);
                float4 r2 = *(const float4*)(res + ci + 4);
                vals[0] += r1.x; vals[1] += r1.y; vals[2] += r1.z; vals[3] += r1.w;
                vals[4] += r2.x; vals[5] += r2.y; vals[6] += r2.z; vals[7] += r2.w;
            }
            *(float4*)(C + ci)     = make_float4(vals[0], vals[1], vals[2], vals[3]);
            *(float4*)(C + ci + 4) = make_float4(vals[4], vals[5], vals[6], vals[7]);
        }
    }
}

// ---------------- flash attention: o23 = softmax(0.125*Q K^T) V --------------
// Per CTA: one 128-row Q tile of one (b,h). q3/k3 are split-192 K-major;
// vT3 is [d, 1024hi |1024lo |1024hi]. 8 warps (4 mw x 2 nw). Online softmax.
#define FA_Q    0u
#define FA_K0   49152u
#define FA_K1   98304u
#define FA_V0   147456u
#define FA_V1   180224u
#define FA_STAT 212992u
#define FA_SMEM 215040

__global__ void __launch_bounds__(256)
flash_attn(const __nv_bfloat16* __restrict__ q3,
           const __nv_bfloat16* __restrict__ k3,
           const __nv_bfloat16* __restrict__ vT3,
           __nv_bfloat16* __restrict__ o23)
{
    extern __shared__ __align__(1024) char smem[];
    uint32_t sb = smem_u32(smem);
    int tid = threadIdx.x, wid = tid >> 5, l = tid & 31;
    int mw = wid & 3, nw = wid >> 2;
    int qt = blockIdx.x, bh = blockIdx.y;
    int b = bh >> 4, h = bh & 15;

    const __nv_bfloat16* Q = q3 + (size_t)bh * 196608 + (size_t)qt * 128 * 192;
    const __nv_bfloat16* K = k3 + (size_t)bh * 196608;
    const __nv_bfloat16* V = vT3 + (size_t)bh * 196608;

    auto load_qk = [&](uint32_t sdst, const __nv_bfloat16* g) {
#pragma unroll
        for (int it = 0; it < 12; it++) {
            int seg = tid + 256 * it;
            int ch = seg >> 9, u = seg & 511, row = u >> 2, c = u & 3;
            cp16(sdst + ch * 8192 + row * 64 + ((c ^ (row & 3)) << 4),
                 g + (size_t)row * 192 + ch * 32 + c * 8);
        }
    };
    auto load_v = [&](uint32_t sdst, int j) {
#pragma unroll
        for (int it = 0; it < 8; it++) {
            int seg = tid + 256 * it;
            int half = seg >> 10, u = seg & 1023;
            int ch = u >> 8, w = u & 255, row = w >> 2, c = w & 3;
            cp16(sdst + half * 16384 + ch * 4096 + row * 64 + ((c ^ (row & 3)) << 4),
                 V + (size_t)row * 3072 + half * 1024 + j * 128 + ch * 32 + c * 8);
        }
    };

    load_qk(sb + FA_Q, Q);
    load_qk(sb + FA_K0, K);
    load_v(sb + FA_V0, 0);
    CP_COMMIT();
    CP_WAIT0();
    __syncthreads();

    float oacc[2][8][4];
#pragma unroll
    for (int i = 0; i < 2; i++)
#pragma unroll
        for (int j = 0; j < 8; j++)
#pragma unroll
            for (int k = 0; k < 4; k++) oacc[i][j][k] = 0.f;
    float m_slot[4], l_slot[4];
#pragma unroll
    for (int s = 0; s < 4; s++) { m_slot[s] = -1e30f; l_slot[s] = 0.f; }

    float* smax = (float*)(smem + FA_STAT);       // [2][128]
    float* ssum = smax + 256;                     // [2][128]
    int rbase = mw * 32 + (l >> 2);               // + (s>>1)*16 + (s&1)*8

    for (int j = 0; j < 8; j++) {
        uint32_t kbuf = sb + ((j & 1) ? FA_K1 : FA_K0);
        uint32_t vbuf = sb + ((j & 1) ? FA_V1 : FA_V0);
        if (j < 7) {
            load_qk(sb + (((j + 1) & 1) ? FA_K1 : FA_K0), K + (size_t)(j + 1) * 128 * 192);
            load_v(sb + (((j + 1) & 1) ? FA_V1 : FA_V0), j + 1);
        }
        CP_COMMIT();

        // ---- S = Q3 . K3^T (widened K=192 does the 3-term split) ----
        float sacc[2][8][4];
#pragma unroll
        for (int i = 0; i < 2; i++)
#pragma unroll
            for (int jj = 0; jj < 8; jj++)
#pragma unroll
                for (int k = 0; k < 4; k++) sacc[i][jj][k] = 0.f;

#pragma unroll
        for (int ch = 0; ch < 6; ch++) {
#pragma unroll
            for (int kh = 0; kh < 2; kh++) {
                uint32_t afr[2][4], bfr[4][4];
#pragma unroll
                for (int i = 0; i < 2; i++) {
                    int row = mw * 32 + i * 16 + (l & 15);
                    int c = (l >> 4) + kh * 2;
                    ldsm4(afr[i], sb + FA_Q + ch * 8192 + row * 64 + ((c ^ (row & 3)) << 4));
                }
#pragma unroll
                for (int j2 = 0; j2 < 4; j2++) {
                    int row = nw * 64 + j2 * 16 + (l & 15);
                    int c = (l >> 4) + kh * 2;
                    ldsm4(bfr[j2], kbuf + ch * 8192 + row * 64 + ((c ^ (row & 3)) << 4));
                }
#pragma unroll
                for (int i = 0; i < 2; i++)
#pragma unroll
                    for (int jj = 0; jj < 8; jj++) {
                        int j2 = jj >> 1, hb = jj & 1;
                        mma16816(sacc[i][jj], afr[i], bfr[j2][hb], bfr[j2][hb + 2]);
                    }
            }
        }

        // ---- online softmax ----
        float mloc[4];
#pragma unroll
        for (int i = 0; i < 2; i++)
#pragma unroll
            for (int h2 = 0; h2 < 2; h2++) {
                float mx = -1e30f;
#pragma unroll
                for (int jj = 0; jj < 8; jj++) {
                    float v0 = sacc[i][jj][h2 * 2] * 0.125f;
                    float v1 = sacc[i][jj][h2 * 2 + 1] * 0.125f;
                    sacc[i][jj][h2 * 2] = v0; sacc[i][jj][h2 * 2 + 1] = v1;
                    mx = fmaxf(mx, fmaxf(v0, v1));
                }
                mx = fmaxf(mx, __shfl_xor_sync(0xffffffffu, mx, 1));
                mx = fmaxf(mx, __shfl_xor_sync(0xffffffffu, mx, 2));
                mloc[i * 2 + h2] = mx;
            }
        if ((l & 3) == 0)
#pragma unroll
            for (int s = 0; s < 4; s++)
                smax[nw * 128 + rbase + (s >> 1) * 16 + (s & 1) * 8] = mloc[s];
        __syncthreads();
        float corr[4];
#pragma unroll
        for (int s = 0; s < 4; s++) {
            int r = rbase + (s >> 1) * 16 + (s & 1) * 8;
            float mt = fmaxf(smax[r], smax[128 + r]);
            float mn = fmaxf(m_slot[s], mt);
            corr[s] = expf(m_slot[s] - mn);
            m_slot[s] = mn;
        }
        float sloc[4] = {0.f, 0.f, 0.f, 0.f};
#pragma unroll
        for (int i = 0; i < 2; i++)
#pragma unroll
            for (int jj = 0; jj < 8; jj++)
#pragma unroll
                for (int h2 = 0; h2 < 2; h2++) {
                    int s = i * 2 + h2;
                    float p0 = expf(sacc[i][jj][h2 * 2] - m_slot[s]);
                    float p1 = expf(sacc[i][jj][h2 * 2 + 1] - m_slot[s]);
                    sacc[i][jj][h2 * 2] = p0; sacc[i][jj][h2 * 2 + 1] = p1;
                    sloc[s] += p0 + p1;
                }
#pragma unroll
        for (int s = 0; s < 4; s++) {
            sloc[s] += __shfl_xor_sync(0xffffffffu, sloc[s], 1);
            sloc[s] += __shfl_xor_sync(0xffffffffu, sloc[s], 2);
        }
        if ((l & 3) == 0)
#pragma unroll
            for (int s = 0; s < 4; s++)
                ssum[nw * 128 + rbase + (s >> 1) * 16 + (s & 1) * 8] = sloc[s];
        __syncthreads();
#pragma unroll
        for (int s = 0; s < 4; s++) {
            int r = rbase + (s >> 1) * 16 + (s & 1) * 8;
            l_slot[s] = l_slot[s] * corr[s] + ssum[r] + ssum[128 + r];
        }
#pragma unroll
        for (int i = 0; i < 2; i++)
#pragma unroll
            for (int jd = 0; jd < 8; jd++)
#pragma unroll
                for (int h2 = 0; h2 < 2; h2++) {
                    oacc[i][jd][h2 * 2]     *= corr[i * 2 + h2];
                    oacc[i][jd][h2 * 2 + 1] *= corr[i * 2 + h2];
                }

        // ---- O += P . V  (3-term split; A-frags direct from sacc) ----
#pragma unroll
        for (int kk = 0; kk < 4; kk++) {
            uint32_t bvh[4][4], bvl[4][4];
            int kh = kk & 1;
            uint32_t choff = (uint32_t)(nw * 2 + (kk >> 1)) * 4096;
#pragma unroll
            for (int j2 = 0; j2 < 4; j2++) {
                int row = j2 * 16 + (l & 15);
                int c = (l >> 4) + kh * 2;
                uint32_t off = (uint32_t)(row * 64 + ((c ^ (row & 3)) << 4));
                ldsm4(bvh[j2], vbuf + choff + off);
                ldsm4(bvl[j2], vbuf + 16384 + choff + off);
            }
#pragma unroll
            for (int i = 0; i < 2; i++) {
                uint32_t ah[4], al[4];
#pragma unroll
                for (int q = 0; q < 4; q++) {
                    int blk = 2 * kk + (q >> 1);
                    int ho = (q & 1) * 2;
                    float p0 = sacc[i][blk][ho], p1 = sacc[i][blk][ho + 1];
                    __nv_bfloat16 h0 = __float2bfloat16(p0), h1 = __float2bfloat16(p1);
                    ah[q] = ((uint32_t)*(uint16_t*)&h1 << 16) | *(uint16_t*)&h0;
                    al[q] = pack_bf(p0 - __bfloat162float(h0), p1 - __bfloat162float(h1));
                }
#pragma unroll
                for (int jd = 0; jd < 8; jd++) {
                    int j2 = jd >> 1, hb = jd & 1;
                    mma16816(oacc[i][jd], ah, bvh[j2][hb], bvh[j2][hb + 2]);
                    mma16816(oacc[i][jd], al, bvh[j2][hb], bvh[j2][hb + 2]);
                    mma16816(oacc[i][jd], ah, bvl[j2][hb], bvl[j2][hb + 2]);
                }
            }
        }
        CP_WAIT0();
        __syncthreads();
    }

    // ---- epilogue: merge nw halves, divide by l, split-write o23 ----------
    float* om = (float*)smem;                      // [128][66] overlays Q
    float* lf = ssum;                              // [128]
    if (nw == 0 && (l & 3) == 0)
#pragma unroll
        for (int s = 0; s < 4; s++)
            lf[rbase + (s >> 1) * 16 + (s & 1) * 8] = l_slot[s];
    if (nw == 1)
#pragma unroll
        for (int i = 0; i < 2; i++)
#pragma unroll
            for (int jd = 0; jd < 8; jd++) {
                int r = mw * 32 + i * 16 + (l >> 2);
                int c = jd * 8 + (l & 3) * 2;
                om[r * 66 + c] = oacc[i][jd][0];
                om[r * 66 + c + 1] = oacc[i][jd][1];
                om[(r + 8) * 66 + c] = oacc[i][jd][2];
                om[(r + 8) * 66 + c + 1] = oacc[i][jd][3];
            }
    __syncthreads();
    if (nw == 0)
#pragma unroll
        for (int i = 0; i < 2; i++)
#pragma unroll
            for (int jd = 0; jd < 8; jd++) {
                int r = mw * 32 + i * 16 + (l >> 2);
                int c = jd * 8 + (l & 3) * 2;
                om[r * 66 + c] += oacc[i][jd][0];
                om[r * 66 + c + 1] += oacc[i][jd][1];
                om[(r + 8) * 66 + c] += oacc[i][jd][2];
                om[(r + 8) * 66 + c + 1] += oacc[i][jd][3];
            }
    __syncthreads();
    size_t rowbase = (size_t)b * 1024 + qt * 128;
#pragma unroll
    for (int p = 0; p < 4; p++) {
        int row = p * 32 + (tid >> 3);
        int c8 = (tid & 7) * 8;
        float inv = 1.f / lf[row];
        __align__(16) __nv_bfloat16 hbv[8];
        __align__(16) __nv_bfloat16 lbv[8];
#pragma unroll
        for (int ii = 0; ii < 8; ii++)
            split_bf16(om[row * 66 + c8 + ii] * inv, hbv[ii], lbv[ii]);
        size_t ci = (rowbase + row) * 3072 + h * 64 + c8;
        *(uint4*)(o23 + ci)        = *(uint4*)hbv;
        *(uint4*)(o23 + ci + 1024) = *(uint4*)hbv;
        *(uint4*)(o23 + ci + 2048) = *(uint4*)lbv;
    }
}

// ---------------- LayerNorm -> split bf16 [hi|hi|lo], K=1024 ----------------
__global__ void ln_split(const float* __restrict__ x, const float* __restrict__ g,
                         const float* __restrict__ b, __nv_bfloat16* __restrict__ out3)
{
    __shared__ float sh1[8], sh2[8];
    int row = blockIdx.x;
    int tid = threadIdx.x;
    const float* p = x + (size_t)row * 1024;
    float v[4];
    float s = 0.f, sq = 0.f;
#pragma unroll
    for (int j = 0; j < 4; j++) {
        v[j] = p[tid + j * 256];
        s += v[j]; sq += v[j] * v[j];
    }
#pragma unroll
    for (int o = 16; o > 0; o >>= 1) {
        s  += __shfl_xor_sync(0xffffffffu, s,  o);
        sq += __shfl_xor_sync(0xffffffffu, sq, o);
    }
    if ((tid & 31) == 0) { sh1[tid >> 5] = s; sh2[tid >> 5] = sq; }
    __syncthreads();
    if (tid == 0) {
        float a = 0.f, c = 0.f;
        for (int i = 0; i < 8; i++) { a += sh1[i]; c += sh2[i]; }
        sh1[0] = a; sh2[0] = c;
    }
    __syncthreads();
    float mean = sh1[0] * (1.f / 1024.f);
    float var  = sh2[0] * (1.f / 1024.f) - mean * mean;
    float rstd = rsqrtf(var + 1e-5f);
    __nv_bfloat16* q = out3 + (size_t)row * 3072;
#pragma unroll
    for (int j = 0; j < 4; j++) {
        int i = tid + j * 256;
        float val = (v[j] - mean) * rstd * g[i] + b[i];
        __nv_bfloat16 hi, lo; split_bf16(val, hi, lo);
        q[i] = hi; q[1024 + i] = hi; q[2048 + i] = lo;
    }
}

// ---------------- weight fp32 [R,K] -> split bf16 [hi|lo|hi] (B-side) -------
__global__ void conv_w3(const float* __restrict__ Wm, __nv_bfloat16* __restrict__ W3,
                        int K, int total)
{
    int idx = blockIdx.x * 256 + threadIdx.x;
    if (idx >= total) return;
    int r = idx / K, k = idx - r * K;
    __nv_bfloat16 hi, lo; split_bf16(Wm[idx], hi, lo);
    size_t base = (size_t)r * 3 * K + k;
    W3[base] = hi; W3[base + K] = lo; W3[base + 2 * K] = hi;
}

// ---------------- qkv -> q3 (A-side), k3 (B-side) ---------------------------
__global__ void qk_split(const float* __restrict__ qkv,
                         __nv_bfloat16* __restrict__ q3, __nv_bfloat16* __restrict__ k3)
{
    size_t idx = (size_t)blockIdx.x * 256 + threadIdx.x;
    int r = (int)(idx >> 11);
    int j = (int)(idx & 2047);
    int isK = j >> 10;
    int c = j & 1023;
    int h = c >> 6, d = c & 63;
    int b = r >> 10, n = r & 1023;
    float val = qkv[(size_t)r * 3072 + j];
    __nv_bfloat16 hi, lo; split_bf16(val, hi, lo);
    size_t base = ((size_t)(b * 16 + h) * 1024 + n) * 192;
    if (isK == 0) { q3[base + d] = hi; q3[base + 64 + d] = hi; q3[base + 128 + d] = lo; }
    else          { k3[base + d] = hi; k3[base + 64 + d] = lo; k3[base + 128 + d] = hi; }
}

// ---------------- v -> vT3 transposed split (B-side) [hi|lo|hi] -------------
__global__ void v_split(const float* __restrict__ qkv, __nv_bfloat16* __restrict__ vT3)
{
    size_t idx = (size_t)blockIdx.x * 256 + threadIdx.x;
    int bh = (int)(idx >> 16);
    int rest = (int)(idx & 65535);
    int d = rest >> 10, n = rest & 1023;
    int b = bh >> 4, h = bh & 15;
    float val = qkv[((size_t)(b * 1024 + n)) * 3072 + 2048 + h * 64 + d];
    __nv_bfloat16 hi, lo; split_bf16(val, hi, lo);
    size_t base = ((size_t)bh * 64 + d) * 3072;
    vT3[base + n] = hi; vT3[base + 1024 + n] = lo; vT3[base + 2048 + n] = hi;
}

// ---------------- template banks -> split bf16 (B-side) ---------------------
__global__ void bank_split(const float* __restrict__ tpl, const float* __restrict__ coef,
                           __nv_bfloat16* __restrict__ W3, int K, int total)
{
    int idx = blockIdx.x * 256 + threadIdx.x;
    if (idx >= total) return;
    float acc = 0.f;
#pragma unroll
    for (int t = 0; t < 16; t++) {
        float ct = 0.5f * (coef[t] + coef[16 + t]);
        acc += tpl[(size_t)t * total + idx] * ct;
    }
    int r = idx / K, k = idx - r * K;
    __nv_bfloat16 hi, lo; split_bf16(acc, hi, lo);
    size_t base = (size_t)r * 3 * K + k;
    W3[base] = hi; W3[base + K] = lo; W3[base + 2 * K] = hi;
}

// ---------------- launcher --------------------------------------------------
extern "C" void kernel_launch(void* const* d_in, const int* in_sizes, int n_in,
                              void* d_out, int out_size)
{
    const float* x      = (const float*)d_in[0];
    const float* ln1_g  = (const float*)d_in[1];
    const float* ln1_b  = (const float*)d_in[2];
    const float* qkv_w  = (const float*)d_in[3];
    const float* proj_w = (const float*)d_in[4];
    const float* proj_b = (const float*)d_in[5];
    const float* ln2_g  = (const float*)d_in[6];
    const float* ln2_b  = (const float*)d_in[7];
    const float* tpl1   = (const float*)d_in[8];
    const float* cf1    = (const float*)d_in[9];
    const float* bias1  = (const float*)d_in[10];
    const float* tpl2   = (const float*)d_in[11];
    const float* cf2    = (const float*)d_in[12];
    const float* bias2  = (const float*)d_in[13];
    float* out = (float*)d_out;

    float *pqkv;
    __nv_bfloat16 *ph3, *pwqkv3, *pwproj3, *pw13, *pw23, *pq3, *pk3, *pvT3, *po23, *py3;
    cudaGetSymbolAddress((void**)&pqkv,   g_qkv);
    cudaGetSymbolAddress((void**)&ph3,    g_h3);
    cudaGetSymbolAddress((void**)&pwqkv3, g_wqkv3);
    cudaGetSymbolAddress((void**)&pwproj3,g_wproj3);
    cudaGetSymbolAddress((void**)&pw13,   g_w13);
    cudaGetSymbolAddress((void**)&pw23,   g_w23);
    cudaGetSymbolAddress((void**)&pq3,    g_q3);
    cudaGetSymbolAddress((void**)&pk3,    g_k3);
    cudaGetSymbolAddress((void**)&pvT3,   g_vT3);
    cudaGetSymbolAddress((void**)&po23,   g_o23);
    cudaGetSymbolAddress((void**)&py3,    g_y3);

    const int SM128 = 128 * 132 * 4;
    cudaFuncSetAttribute(mm_gemm<128>, cudaFuncAttributeMaxDynamicSharedMemorySize, SM128);
    cudaFuncSetAttribute(flash_attn, cudaFuncAttributeMaxDynamicSharedMemorySize, FA_SMEM);

    // 1. LN1(x) -> h3 (split)
    ln_split<<<8192, 256>>>(x, ln1_g, ln1_b, ph3);
    // 2. weight conversions + banks
    conv_w3<<<(3072 * 1024 + 255) / 256, 256>>>(qkv_w, pwqkv3, 1024, 3072 * 1024);
    conv_w3<<<(1024 * 1024 + 255) / 256, 256>>>(proj_w, pwproj3, 1024, 1024 * 1024);
    bank_split<<<(4096 * 1024 + 255) / 256, 256>>>(tpl1, cf1, pw13, 1024, 4096 * 1024);
    bank_split<<<(1024 * 4096 + 255) / 256, 256>>>(tpl2, cf2, pw23, 4096, 1024 * 4096);

    // 3. qkv = h3 @ wqkv3^T  [8192,3072] fp32
    mm_gemm<128><<<dim3(24, 64, 1), 256, SM128>>>(
        ph3, pwqkv3, 3072, 0, 0,
        pqkv, nullptr, 3072, 0, 1, 0, 0, nullptr, nullptr, 1.f, 0);

    // 4. split qkv -> q3/k3/vT3
    qk_split<<<(int)(((size_t)8192 * 2048) / 256), 256>>>(pqkv, pq3, pk3);
    v_split<<<(int)(((size_t)128 * 64 * 1024) / 256), 256>>>(pqkv, pvT3);

    // 5-7. fused attention -> o23 (split)
    flash_attn<<<dim3(8, 128), 256, FA_SMEM>>>(pq3, pk3, pvT3, po23);

    // 8. out = x + o2_3 @ wproj3^T + proj_b
    mm_gemm<128><<<dim3(8, 64, 1), 256, SM128>>>(
        po23, pwproj3, 3072, 0, 0,
        out, nullptr, 1024, 0, 1, 0, 0, proj_b, x, 1.f, 0);

    // 9. LN2(out) -> h3 (split)
    ln_split<<<8192, 256>>>(out, ln2_g, ln2_b, ph3);

    // 10. y3(split) = gelu(h3 @ w13^T + bias1)  [8192,4096]
    mm_gemm<128><<<dim3(32, 64, 1), 256, SM128>>>(
        ph3, pw13, 3072, 0, 0,
        nullptr, py3, 12288, 4096, 1, 0, 0, bias1, nullptr, 1.f, 1);

    // 11. out = out + y3 @ w23^T + bias2
    mm_gemm<128><<<dim3(8, 64, 1), 256, SM128>>>(
        py3, pw23, 12288, 0, 0,
        out, nullptr, 1024, 0, 1, 0, 0, bias2, out, 1.f, 0);
}

// round 6
// speedup vs baseline: 3.2482x; 1.2396x over previous
#include <cuda_runtime.h>
#include <cuda_bf16.h>
#include <cstdint>
#include <math.h>

#define MROWS 8192

// ---------------- scratch (static device globals) ---------------------------
__device__ float g_qkv[(size_t)MROWS * 3072];               // qkv out fp32
__device__ __nv_bfloat16 g_h3    [(size_t)MROWS * 3072];    // LN out, split
__device__ __nv_bfloat16 g_wqkv3 [(size_t)3072 * 3072];
__device__ __nv_bfloat16 g_wproj3[(size_t)1024 * 3072];
__device__ __nv_bfloat16 g_w13   [(size_t)4096 * 3072];
__device__ __nv_bfloat16 g_w23   [(size_t)1024 * 12288];
__device__ __nv_bfloat16 g_q3    [(size_t)128 * 1024 * 192];
__device__ __nv_bfloat16 g_k3    [(size_t)128 * 1024 * 192];
__device__ __nv_bfloat16 g_vT3   [(size_t)128 * 64 * 3072];
__device__ __nv_bfloat16 g_o23   [(size_t)MROWS * 3072];
__device__ __nv_bfloat16 g_y3    [(size_t)MROWS * 12288];

// ---------------- helpers ----------------------------------------------------
__device__ __forceinline__ uint32_t smem_u32(const void* p) {
    uint32_t a;
    asm("{ .reg .u64 t; cvta.to.shared.u64 t, %1; cvt.u32.u64 %0, t; }" : "=r"(a) : "l"(p));
    return a;
}
__device__ __forceinline__ void cp16(uint32_t saddr, const void* g) {
    asm volatile("cp.async.cg.shared.global [%0], [%1], 16;" :: "r"(saddr), "l"(g));
}
#define CP_COMMIT() asm volatile("cp.async.commit_group;" ::: "memory")
#define CP_WAIT0()  asm volatile("cp.async.wait_group 0;" ::: "memory")

__device__ __forceinline__ void ldsm4(uint32_t* r, uint32_t a) {
    asm volatile("ldmatrix.sync.aligned.m8n8.x4.shared.b16 {%0,%1,%2,%3}, [%4];"
                 : "=r"(r[0]), "=r"(r[1]), "=r"(r[2]), "=r"(r[3]) : "r"(a));
}
__device__ __forceinline__ void mma16816(float* c, const uint32_t* a, uint32_t b0, uint32_t b1) {
    asm volatile("mma.sync.aligned.m16n8k16.row.col.f32.bf16.bf16.f32 "
                 "{%0,%1,%2,%3}, {%4,%5,%6,%7}, {%8,%9}, {%0,%1,%2,%3};"
                 : "+f"(c[0]), "+f"(c[1]), "+f"(c[2]), "+f"(c[3])
                 : "r"(a[0]), "r"(a[1]), "r"(a[2]), "r"(a[3]), "r"(b0), "r"(b1));
}
__device__ __forceinline__ void split_bf16(float v, __nv_bfloat16& hi, __nv_bfloat16& lo) {
    hi = __float2bfloat16(v);
    lo = __float2bfloat16(v - __bfloat162float(hi));
}
__device__ __forceinline__ uint32_t pack_bf(float a, float b) {
    __nv_bfloat16 x = __float2bfloat16(a), y = __float2bfloat16(b);
    return ((uint32_t)*(uint16_t*)&y << 16) | *(uint16_t*)&x;
}

// ---------------- HMMA split GEMM: C = alpha*(A3 @ B3^T) ---------------------
// A3 [M,K3], B3 [128-tile,K3] row-major bf16. CTA tile 128x128, BK=64,
// 2-stage cp.async ring, 8 warps (4x2), m16n8k16 HMMA.
__global__ void __launch_bounds__(256)
mm_gemm(const __nv_bfloat16* __restrict__ A, const __nv_bfloat16* __restrict__ B,
        int K3,
        float* __restrict__ C, __nv_bfloat16* __restrict__ O3,
        long long ldc, int Ksp,
        const float* __restrict__ bias, const float* __restrict__ res,
        int gelu_f)
{
    extern __shared__ __align__(1024) char smem[];
    const int STAGE = 32768;                  // A 16KB + B 16KB (128 rows x 128B)

    int tid = threadIdx.x;
    int wid = tid >> 5;
    int l   = tid & 31;
    int mw  = wid & 3;
    int nw  = wid >> 2;

    int bn = blockIdx.x, bm = blockIdx.y;
    A += (size_t)bm * 128 * K3;
    B += (size_t)bn * 128 * K3;

    uint32_t sbase = smem_u32(smem);

    // cp.async per-thread offsets: 16KB tile = 1024 x 16B chunks, 4 per thread
    uint32_t t_soff[4]; size_t t_goff[4];
#pragma unroll
    for (int i = 0; i < 4; i++) {
        int id = tid + 256 * i;
        int row = id >> 3, c = id & 7;
        t_soff[i] = (uint32_t)(row * 128 + ((c ^ (row & 7)) << 4));
        t_goff[i] = (size_t)row * K3 + c * 8;
    }
    // ldmatrix per-lane offsets (4 k16 steps per BK=64)
    uint32_t lma[2][4], lmb[4][4];
#pragma unroll
    for (int i = 0; i < 2; i++)
#pragma unroll
        for (int kh = 0; kh < 4; kh++) {
            int row = mw * 32 + i * 16 + (l & 15);
            int c = (l >> 4) + kh * 2;
            lma[i][kh] = (uint32_t)(row * 128 + ((c ^ (row & 7)) << 4));
        }
#pragma unroll
    for (int j2 = 0; j2 < 4; j2++)
#pragma unroll
        for (int kh = 0; kh < 4; kh++) {
            int row = nw * 64 + j2 * 16 + (l & 15);
            int c = (l >> 4) + kh * 2;
            lmb[j2][kh] = (uint32_t)(16384 + row * 128 + ((c ^ (row & 7)) << 4));
        }

    float acc[2][8][4];
#pragma unroll
    for (int i = 0; i < 2; i++)
#pragma unroll
        for (int j = 0; j < 8; j++)
#pragma unroll
            for (int k = 0; k < 4; k++) acc[i][j][k] = 0.f;

    int nk = K3 >> 6;   // BK=64

    auto issue = [&](int ks) {
        if (ks < nk) {
            uint32_t st = sbase + (ks & 1) * STAGE;
            const __nv_bfloat16* Ag = A + (size_t)ks * 64;
            const __nv_bfloat16* Bg = B + (size_t)ks * 64;
#pragma unroll
            for (int i = 0; i < 4; i++) cp16(st + t_soff[i], Ag + t_goff[i]);
#pragma unroll
            for (int i = 0; i < 4; i++) cp16(st + 16384 + t_soff[i], Bg + t_goff[i]);
        }
        CP_COMMIT();
    };

    issue(0);

    for (int ks = 0; ks < nk; ks++) {
        CP_WAIT0();
        __syncthreads();
        issue(ks + 1);
        uint32_t st = sbase + (ks & 1) * STAGE;
#pragma unroll
        for (int kh = 0; kh < 4; kh++) {
            uint32_t afr[2][4];
#pragma unroll
            for (int i = 0; i < 2; i++) ldsm4(afr[i], st + lma[i][kh]);
            uint32_t bfr[4][4];
#pragma unroll
            for (int j2 = 0; j2 < 4; j2++) ldsm4(bfr[j2], st + lmb[j2][kh]);
#pragma unroll
            for (int i = 0; i < 2; i++)
#pragma unroll
                for (int j = 0; j < 8; j++) {
                    int j2 = j >> 1, hb = j & 1;
                    mma16816(acc[i][j], afr[i], bfr[j2][hb], bfr[j2][hb + 2]);
                }
        }
    }
    __syncthreads();

    // ---- epilogue: regs -> SMEM (transpose) -> coalesced GMEM --------------
    const int pitch = 132;
    float* smf = (float*)smem;
#pragma unroll
    for (int i = 0; i < 2; i++)
#pragma unroll
        for (int j = 0; j < 8; j++) {
            int r = mw * 32 + i * 16 + (l >> 2);
            int c = nw * 64 + j * 8 + (l & 3) * 2;
            *(float2*)&smf[r * pitch + c]       = make_float2(acc[i][j][0], acc[i][j][1]);
            *(float2*)&smf[(r + 8) * pitch + c] = make_float2(acc[i][j][2], acc[i][j][3]);
        }
    __syncthreads();

    int m0 = bm * 128;
#pragma unroll
    for (int p = 0; p < 8; p++) {
        int row = p * 16 + (tid >> 4);
        int c8 = (tid & 15) * 8;
        float vals[8];
#pragma unroll
        for (int i = 0; i < 8; i++) vals[i] = smf[row * pitch + c8 + i];
#pragma unroll
        for (int i = 0; i < 8; i++) {
            float v = vals[i];
            if (bias) v += bias[bn * 128 + c8 + i];
            if (gelu_f) v = 0.5f * v * (1.f + erff(v * 0.70710678118654752f));
            vals[i] = v;
        }
        size_t ci = (size_t)(m0 + row) * ldc + bn * 128 + c8;
        if (O3) {
            __align__(16) __nv_bfloat16 hb[8];
            __align__(16) __nv_bfloat16 lb[8];
#pragma unroll
            for (int i = 0; i < 8; i++) split_bf16(vals[i], hb[i], lb[i]);
            *(uint4*)(O3 + ci)                   = *(uint4*)hb;
            *(uint4*)(O3 + ci + (size_t)Ksp)     = *(uint4*)hb;
            *(uint4*)(O3 + ci + 2 * (size_t)Ksp) = *(uint4*)lb;
        } else {
            if (res) {
                float4 r1 = *(const float4*)(res + ci);
                float4 r2 = *(const float4*)(res + ci + 4);
                vals[0] += r1.x; vals[1] += r1.y; vals[2] += r1.z; vals[3] += r1.w;
                vals[4] += r2.x; vals[5] += r2.y; vals[6] += r2.z; vals[7] += r2.w;
            }
            *(float4*)(C + ci)     = make_float4(vals[0], vals[1], vals[2], vals[3]);
            *(float4*)(C + ci + 4) = make_float4(vals[4], vals[5], vals[6], vals[7]);
        }
    }
}

// ---------------- flash attention: o23 = softmax(0.125*Q K^T) V --------------
#define FA_Q    0u
#define FA_K0   49152u
#define FA_K1   98304u
#define FA_V0   147456u
#define FA_V1   180224u
#define FA_STAT 212992u
#define FA_SMEM 215040

__global__ void __launch_bounds__(256)
flash_attn(const __nv_bfloat16* __restrict__ q3,
           const __nv_bfloat16* __restrict__ k3,
           const __nv_bfloat16* __restrict__ vT3,
           __nv_bfloat16* __restrict__ o23)
{
    extern __shared__ __align__(1024) char smem[];
    uint32_t sb = smem_u32(smem);
    int tid = threadIdx.x, wid = tid >> 5, l = tid & 31;
    int mw = wid & 3, nw = wid >> 2;
    int qt = blockIdx.x, bh = blockIdx.y;
    int b = bh >> 4, h = bh & 15;

    const __nv_bfloat16* Q = q3 + (size_t)bh * 196608 + (size_t)qt * 128 * 192;
    const __nv_bfloat16* K = k3 + (size_t)bh * 196608;
    const __nv_bfloat16* V = vT3 + (size_t)bh * 196608;

    auto load_qk = [&](uint32_t sdst, const __nv_bfloat16* g) {
#pragma unroll
        for (int it = 0; it < 12; it++) {
            int seg = tid + 256 * it;
            int ch = seg >> 9, u = seg & 511, row = u >> 2, c = u & 3;
            cp16(sdst + ch * 8192 + row * 64 + ((c ^ (row & 3)) << 4),
                 g + (size_t)row * 192 + ch * 32 + c * 8);
        }
    };
    auto load_v = [&](uint32_t sdst, int j) {
#pragma unroll
        for (int it = 0; it < 8; it++) {
            int seg = tid + 256 * it;
            int half = seg >> 10, u = seg & 1023;
            int ch = u >> 8, w = u & 255, row = w >> 2, c = w & 3;
            cp16(sdst + half * 16384 + ch * 4096 + row * 64 + ((c ^ (row & 3)) << 4),
                 V + (size_t)row * 3072 + half * 1024 + j * 128 + ch * 32 + c * 8);
        }
    };

    load_qk(sb + FA_Q, Q);
    load_qk(sb + FA_K0, K);
    load_v(sb + FA_V0, 0);
    CP_COMMIT();
    CP_WAIT0();
    __syncthreads();

    float oacc[2][8][4];
#pragma unroll
    for (int i = 0; i < 2; i++)
#pragma unroll
        for (int j = 0; j < 8; j++)
#pragma unroll
            for (int k = 0; k < 4; k++) oacc[i][j][k] = 0.f;
    float m_slot[4], l_slot[4];
#pragma unroll
    for (int s = 0; s < 4; s++) { m_slot[s] = -1e30f; l_slot[s] = 0.f; }

    float* smax = (float*)(smem + FA_STAT);
    float* ssum = smax + 256;
    int rbase = mw * 32 + (l >> 2);

    for (int j = 0; j < 8; j++) {
        uint32_t kbuf = sb + ((j & 1) ? FA_K1 : FA_K0);
        uint32_t vbuf = sb + ((j & 1) ? FA_V1 : FA_V0);
        if (j < 7) {
            load_qk(sb + (((j + 1) & 1) ? FA_K1 : FA_K0), K + (size_t)(j + 1) * 128 * 192);
            load_v(sb + (((j + 1) & 1) ? FA_V1 : FA_V0), j + 1);
        }
        CP_COMMIT();

        float sacc[2][8][4];
#pragma unroll
        for (int i = 0; i < 2; i++)
#pragma unroll
            for (int jj = 0; jj < 8; jj++)
#pragma unroll
                for (int k = 0; k < 4; k++) sacc[i][jj][k] = 0.f;

#pragma unroll
        for (int ch = 0; ch < 6; ch++) {
#pragma unroll
            for (int kh = 0; kh < 2; kh++) {
                uint32_t afr[2][4], bfr[4][4];
#pragma unroll
                for (int i = 0; i < 2; i++) {
                    int row = mw * 32 + i * 16 + (l & 15);
                    int c = (l >> 4) + kh * 2;
                    ldsm4(afr[i], sb + FA_Q + ch * 8192 + row * 64 + ((c ^ (row & 3)) << 4));
                }
#pragma unroll
                for (int j2 = 0; j2 < 4; j2++) {
                    int row = nw * 64 + j2 * 16 + (l & 15);
                    int c = (l >> 4) + kh * 2;
                    ldsm4(bfr[j2], kbuf + ch * 8192 + row * 64 + ((c ^ (row & 3)) << 4));
                }
#pragma unroll
                for (int i = 0; i < 2; i++)
#pragma unroll
                    for (int jj = 0; jj < 8; jj++) {
                        int j2 = jj >> 1, hb = jj & 1;
                        mma16816(sacc[i][jj], afr[i], bfr[j2][hb], bfr[j2][hb + 2]);
                    }
            }
        }

        // ---- online softmax ----
        float mloc[4];
#pragma unroll
        for (int i = 0; i < 2; i++)
#pragma unroll
            for (int h2 = 0; h2 < 2; h2++) {
                float mx = -1e30f;
#pragma unroll
                for (int jj = 0; jj < 8; jj++) {
                    float v0 = sacc[i][jj][h2 * 2] * 0.125f;
                    float v1 = sacc[i][jj][h2 * 2 + 1] * 0.125f;
                    sacc[i][jj][h2 * 2] = v0; sacc[i][jj][h2 * 2 + 1] = v1;
                    mx = fmaxf(mx, fmaxf(v0, v1));
                }
                mx = fmaxf(mx, __shfl_xor_sync(0xffffffffu, mx, 1));
                mx = fmaxf(mx, __shfl_xor_sync(0xffffffffu, mx, 2));
                mloc[i * 2 + h2] = mx;
            }
        if ((l & 3) == 0)
#pragma unroll
            for (int s = 0; s < 4; s++)
                smax[nw * 128 + rbase + (s >> 1) * 16 + (s & 1) * 8] = mloc[s];
        __syncthreads();
        float corr[4];
#pragma unroll
        for (int s = 0; s < 4; s++) {
            int r = rbase + (s >> 1) * 16 + (s & 1) * 8;
            float mt = fmaxf(smax[r], smax[128 + r]);
            float mn = fmaxf(m_slot[s], mt);
            corr[s] = __expf(m_slot[s] - mn);
            m_slot[s] = mn;
        }
        float sloc[4] = {0.f, 0.f, 0.f, 0.f};
#pragma unroll
        for (int i = 0; i < 2; i++)
#pragma unroll
            for (int jj = 0; jj < 8; jj++)
#pragma unroll
                for (int h2 = 0; h2 < 2; h2++) {
                    int s = i * 2 + h2;
                    float p0 = __expf(sacc[i][jj][h2 * 2] - m_slot[s]);
                    float p1 = __expf(sacc[i][jj][h2 * 2 + 1] - m_slot[s]);
                    sacc[i][jj][h2 * 2] = p0; sacc[i][jj][h2 * 2 + 1] = p1;
                    sloc[s] += p0 + p1;
                }
#pragma unroll
        for (int s = 0; s < 4; s++) {
            sloc[s] += __shfl_xor_sync(0xffffffffu, sloc[s], 1);
            sloc[s] += __shfl_xor_sync(0xffffffffu, sloc[s], 2);
        }
        if ((l & 3) == 0)
#pragma unroll
            for (int s = 0; s < 4; s++)
                ssum[nw * 128 + rbase + (s >> 1) * 16 + (s & 1) * 8] = sloc[s];
        __syncthreads();
#pragma unroll
        for (int s = 0; s < 4; s++) {
            int r = rbase + (s >> 1) * 16 + (s & 1) * 8;
            l_slot[s] = l_slot[s] * corr[s] + ssum[r] + ssum[128 + r];
        }
#pragma unroll
        for (int i = 0; i < 2; i++)
#pragma unroll
            for (int jd = 0; jd < 8; jd++)
#pragma unroll
                for (int h2 = 0; h2 < 2; h2++) {
                    oacc[i][jd][h2 * 2]     *= corr[i * 2 + h2];
                    oacc[i][jd][h2 * 2 + 1] *= corr[i * 2 + h2];
                }

        // ---- O += P . V (3-term split) ----
#pragma unroll
        for (int kk = 0; kk < 4; kk++) {
            uint32_t bvh[4][4], bvl[4][4];
            int kh = kk & 1;
            uint32_t choff = (uint32_t)(nw * 2 + (kk >> 1)) * 4096;
#pragma unroll
            for (int j2 = 0; j2 < 4; j2++) {
                int row = j2 * 16 + (l & 15);
                int c = (l >> 4) + kh * 2;
                uint32_t off = (uint32_t)(row * 64 + ((c ^ (row & 3)) << 4));
                ldsm4(bvh[j2], vbuf + choff + off);
                ldsm4(bvl[j2], vbuf + 16384 + choff + off);
            }
#pragma unroll
            for (int i = 0; i < 2; i++) {
                uint32_t ah[4], al[4];
#pragma unroll
                for (int q = 0; q < 4; q++) {
                    int blk = 2 * kk + (q >> 1);
                    int ho = (q & 1) * 2;
                    float p0 = sacc[i][blk][ho], p1 = sacc[i][blk][ho + 1];
                    __nv_bfloat16 h0 = __float2bfloat16(p0), h1 = __float2bfloat16(p1);
                    ah[q] = ((uint32_t)*(uint16_t*)&h1 << 16) | *(uint16_t*)&h0;
                    al[q] = pack_bf(p0 - __bfloat162float(h0), p1 - __bfloat162float(h1));
                }
#pragma unroll
                for (int jd = 0; jd < 8; jd++) {
                    int j2 = jd >> 1, hb = jd & 1;
                    mma16816(oacc[i][jd], ah, bvh[j2][hb], bvh[j2][hb + 2]);
                    mma16816(oacc[i][jd], al, bvh[j2][hb], bvh[j2][hb + 2]);
                    mma16816(oacc[i][jd], ah, bvl[j2][hb], bvl[j2][hb + 2]);
                }
            }
        }
        CP_WAIT0();
        __syncthreads();
    }

    // ---- epilogue ----
    float* om = (float*)smem;
    float* lf = ssum;
    if (nw == 0 && (l & 3) == 0)
#pragma unroll
        for (int s = 0; s < 4; s++)
            lf[rbase + (s >> 1) * 16 + (s & 1) * 8] = l_slot[s];
    if (nw == 1)
#pragma unroll
        for (int i = 0; i < 2; i++)
#pragma unroll
            for (int jd = 0; jd < 8; jd++) {
                int r = mw * 32 + i * 16 + (l >> 2);
                int c = jd * 8 + (l & 3) * 2;
                om[r * 66 + c] = oacc[i][jd][0];
                om[r * 66 + c + 1] = oacc[i][jd][1];
                om[(r + 8) * 66 + c] = oacc[i][jd][2];
                om[(r + 8) * 66 + c + 1] = oacc[i][jd][3];
            }
    __syncthreads();
    if (nw == 0)
#pragma unroll
        for (int i = 0; i < 2; i++)
#pragma unroll
            for (int jd = 0; jd < 8; jd++) {
                int r = mw * 32 + i * 16 + (l >> 2);
                int c = jd * 8 + (l & 3) * 2;
                om[r * 66 + c] += oacc[i][jd][0];
                om[r * 66 + c + 1] += oacc[i][jd][1];
                om[(r + 8) * 66 + c] += oacc[i][jd][2];
                om[(r + 8) * 66 + c + 1] += oacc[i][jd][3];
            }
    __syncthreads();
    size_t rowbase = (size_t)b * 1024 + qt * 128;
#pragma unroll
    for (int p = 0; p < 4; p++) {
        int row = p * 32 + (tid >> 3);
        int c8 = (tid & 7) * 8;
        float inv = 1.f / lf[row];
        __align__(16) __nv_bfloat16 hbv[8];
        __align__(16) __nv_bfloat16 lbv[8];
#pragma unroll
        for (int ii = 0; ii < 8; ii++)
            split_bf16(om[row * 66 + c8 + ii] * inv, hbv[ii], lbv[ii]);
        size_t ci = (rowbase + row) * 3072 + h * 64 + c8;
        *(uint4*)(o23 + ci)        = *(uint4*)hbv;
        *(uint4*)(o23 + ci + 1024) = *(uint4*)hbv;
        *(uint4*)(o23 + ci + 2048) = *(uint4*)lbv;
    }
}

// ---------------- LayerNorm -> split bf16 [hi|hi|lo], K=1024 ----------------
__global__ void ln_split(const float* __restrict__ x, const float* __restrict__ g,
                         const float* __restrict__ b, __nv_bfloat16* __restrict__ out3)
{
    __shared__ float sh1[8], sh2[8];
    int row = blockIdx.x;
    int tid = threadIdx.x;
    const float* p = x + (size_t)row * 1024;
    float v[4];
    float s = 0.f, sq = 0.f;
#pragma unroll
    for (int j = 0; j < 4; j++) {
        v[j] = p[tid + j * 256];
        s += v[j]; sq += v[j] * v[j];
    }
#pragma unroll
    for (int o = 16; o > 0; o >>= 1) {
        s  += __shfl_xor_sync(0xffffffffu, s,  o);
        sq += __shfl_xor_sync(0xffffffffu, sq, o);
    }
    if ((tid & 31) == 0) { sh1[tid >> 5] = s; sh2[tid >> 5] = sq; }
    __syncthreads();
    if (tid == 0) {
        float a = 0.f, c = 0.f;
        for (int i = 0; i < 8; i++) { a += sh1[i]; c += sh2[i]; }
        sh1[0] = a; sh2[0] = c;
    }
    __syncthreads();
    float mean = sh1[0] * (1.f / 1024.f);
    float var  = sh2[0] * (1.f / 1024.f) - mean * mean;
    float rstd = rsqrtf(var + 1e-5f);
    __nv_bfloat16* q = out3 + (size_t)row * 3072;
#pragma unroll
    for (int j = 0; j < 4; j++) {
        int i = tid + j * 256;
        float val = (v[j] - mean) * rstd * g[i] + b[i];
        __nv_bfloat16 hi, lo; split_bf16(val, hi, lo);
        q[i] = hi; q[1024 + i] = hi; q[2048 + i] = lo;
    }
}

// ---------------- weight fp32 [R,K] -> split bf16 [hi|lo|hi] (B-side) -------
__global__ void conv_w3(const float* __restrict__ Wm, __nv_bfloat16* __restrict__ W3,
                        int K, int total)
{
    int idx = blockIdx.x * 256 + threadIdx.x;
    if (idx >= total) return;
    int r = idx / K, k = idx - r * K;
    __nv_bfloat16 hi, lo; split_bf16(Wm[idx], hi, lo);
    size_t base = (size_t)r * 3 * K + k;
    W3[base] = hi; W3[base + K] = lo; W3[base + 2 * K] = hi;
}

// ---------------- qkv -> q3 (A-side), k3 (B-side) ---------------------------
__global__ void qk_split(const float* __restrict__ qkv,
                         __nv_bfloat16* __restrict__ q3, __nv_bfloat16* __restrict__ k3)
{
    size_t idx = (size_t)blockIdx.x * 256 + threadIdx.x;
    int r = (int)(idx >> 11);
    int j = (int)(idx & 2047);
    int isK = j >> 10;
    int c = j & 1023;
    int h = c >> 6, d = c & 63;
    int b = r >> 10, n = r & 1023;
    float val = qkv[(size_t)r * 3072 + j];
    __nv_bfloat16 hi, lo; split_bf16(val, hi, lo);
    size_t base = ((size_t)(b * 16 + h) * 1024 + n) * 192;
    if (isK == 0) { q3[base + d] = hi; q3[base + 64 + d] = hi; q3[base + 128 + d] = lo; }
    else          { k3[base + d] = hi; k3[base + 64 + d] = lo; k3[base + 128 + d] = hi; }
}

// ---------------- v -> vT3 transposed split (B-side) [hi|lo|hi] -------------
__global__ void v_split(const float* __restrict__ qkv, __nv_bfloat16* __restrict__ vT3)
{
    size_t idx = (size_t)blockIdx.x * 256 + threadIdx.x;
    int bh = (int)(idx >> 16);
    int rest = (int)(idx & 65535);
    int d = rest >> 10, n = rest & 1023;
    int b = bh >> 4, h = bh & 15;
    float val = qkv[((size_t)(b * 1024 + n)) * 3072 + 2048 + h * 64 + d];
    __nv_bfloat16 hi, lo; split_bf16(val, hi, lo);
    size_t base = ((size_t)bh * 64 + d) * 3072;
    vT3[base + n] = hi; vT3[base + 1024 + n] = lo; vT3[base + 2048 + n] = hi;
}

// ---------------- template banks -> split bf16 (B-side) ---------------------
__global__ void bank_split(const float* __restrict__ tpl, const float* __restrict__ coef,
                           __nv_bfloat16* __restrict__ W3, int K, int total)
{
    int idx = blockIdx.x * 256 + threadIdx.x;
    if (idx >= total) return;
    float acc = 0.f;
#pragma unroll
    for (int t = 0; t < 16; t++) {
        float ct = 0.5f * (coef[t] + coef[16 + t]);
        acc += tpl[(size_t)t * total + idx] * ct;
    }
    int r = idx / K, k = idx - r * K;
    __nv_bfloat16 hi, lo; split_bf16(acc, hi, lo);
    size_t base = (size_t)r * 3 * K + k;
    W3[base] = hi; W3[base + K] = lo; W3[base + 2 * K] = hi;
}

// ---------------- launcher --------------------------------------------------
extern "C" void kernel_launch(void* const* d_in, const int* in_sizes, int n_in,
                              void* d_out, int out_size)
{
    const float* x      = (const float*)d_in[0];
    const float* ln1_g  = (const float*)d_in[1];
    const float* ln1_b  = (const float*)d_in[2];
    const float* qkv_w  = (const float*)d_in[3];
    const float* proj_w = (const float*)d_in[4];
    const float* proj_b = (const float*)d_in[5];
    const float* ln2_g  = (const float*)d_in[6];
    const float* ln2_b  = (const float*)d_in[7];
    const float* tpl1   = (const float*)d_in[8];
    const float* cf1    = (const float*)d_in[9];
    const float* bias1  = (const float*)d_in[10];
    const float* tpl2   = (const float*)d_in[11];
    const float* cf2    = (const float*)d_in[12];
    const float* bias2  = (const float*)d_in[13];
    float* out = (float*)d_out;

    float *pqkv;
    __nv_bfloat16 *ph3, *pwqkv3, *pwproj3, *pw13, *pw23, *pq3, *pk3, *pvT3, *po23, *py3;
    cudaGetSymbolAddress((void**)&pqkv,   g_qkv);
    cudaGetSymbolAddress((void**)&ph3,    g_h3);
    cudaGetSymbolAddress((void**)&pwqkv3, g_wqkv3);
    cudaGetSymbolAddress((void**)&pwproj3,g_wproj3);
    cudaGetSymbolAddress((void**)&pw13,   g_w13);
    cudaGetSymbolAddress((void**)&pw23,   g_w23);
    cudaGetSymbolAddress((void**)&pq3,    g_q3);
    cudaGetSymbolAddress((void**)&pk3,    g_k3);
    cudaGetSymbolAddress((void**)&pvT3,   g_vT3);
    cudaGetSymbolAddress((void**)&po23,   g_o23);
    cudaGetSymbolAddress((void**)&py3,    g_y3);

    const int SM128 = 128 * 132 * 4;    // 67584 (> 2*32768 ring)
    cudaFuncSetAttribute(mm_gemm, cudaFuncAttributeMaxDynamicSharedMemorySize, SM128);
    cudaFuncSetAttribute(flash_attn, cudaFuncAttributeMaxDynamicSharedMemorySize, FA_SMEM);

    // 1. LN1(x) -> h3 ;  qkv weights
    ln_split<<<8192, 256>>>(x, ln1_g, ln1_b, ph3);
    conv_w3<<<(3072 * 1024 + 255) / 256, 256>>>(qkv_w, pwqkv3, 1024, 3072 * 1024);

    // 2. qkv = h3 @ wqkv3^T  [8192,3072] fp32   (in ncu capture window)
    mm_gemm<<<dim3(24, 64), 256, SM128>>>(
        ph3, pwqkv3, 3072, pqkv, nullptr, 3072, 0, nullptr, nullptr, 0);

    // 3. split qkv -> q3/k3/vT3
    qk_split<<<(int)(((size_t)8192 * 2048) / 256), 256>>>(pqkv, pq3, pk3);
    v_split<<<(int)(((size_t)128 * 64 * 1024) / 256), 256>>>(pqkv, pvT3);

    // 4. fused attention -> o23 (split)
    flash_attn<<<dim3(8, 128), 256, FA_SMEM>>>(pq3, pk3, pvT3, po23);

    // 5. proj weights + out = x + o23 @ wproj3^T + proj_b
    conv_w3<<<(1024 * 1024 + 255) / 256, 256>>>(proj_w, pwproj3, 1024, 1024 * 1024);
    mm_gemm<<<dim3(8, 64), 256, SM128>>>(
        po23, pwproj3, 3072, out, nullptr, 1024, 0, proj_b, x, 0);

    // 6. LN2(out) -> h3 ; MLP banks
    ln_split<<<8192, 256>>>(out, ln2_g, ln2_b, ph3);
    bank_split<<<(4096 * 1024 + 255) / 256, 256>>>(tpl1, cf1, pw13, 1024, 4096 * 1024);
    bank_split<<<(1024 * 4096 + 255) / 256, 256>>>(tpl2, cf2, pw23, 4096, 1024 * 4096);

    // 7. y3(split) = gelu(h3 @ w13^T + bias1)  [8192,4096]
    mm_gemm<<<dim3(32, 64), 256, SM128>>>(
        ph3, pw13, 3072, nullptr, py3, 12288, 4096, bias1, nullptr, 1);

    // 8. out = out + y3 @ w23^T + bias2
    mm_gemm<<<dim3(8, 64), 256, SM128>>>(
        py3, pw23, 12288, out, nullptr, 1024, 0, bias2, out, 0);
}

// round 7
// speedup vs baseline: 3.2977x; 1.0152x over previous
#include <cuda_runtime.h>
#include <cuda_bf16.h>
#include <cstdint>
#include <math.h>

#define MROWS 8192

// ---------------- scratch (static device globals) ---------------------------
__device__ __nv_bfloat16 g_h3    [(size_t)MROWS * 3072];    // LN out, split
__device__ __nv_bfloat16 g_wqkv3 [(size_t)3072 * 3072];
__device__ __nv_bfloat16 g_wproj3[(size_t)1024 * 3072];
__device__ __nv_bfloat16 g_w13   [(size_t)4096 * 3072];
__device__ __nv_bfloat16 g_w23   [(size_t)1024 * 12288];
__device__ __nv_bfloat16 g_q3    [(size_t)128 * 1024 * 192];
__device__ __nv_bfloat16 g_k3    [(size_t)128 * 1024 * 192];
__device__ __nv_bfloat16 g_vT3   [(size_t)128 * 64 * 3072];
__device__ __nv_bfloat16 g_o23   [(size_t)MROWS * 3072];
__device__ __nv_bfloat16 g_y3    [(size_t)MROWS * 12288];

// ---------------- helpers ----------------------------------------------------
__device__ __forceinline__ uint32_t smem_u32(const void* p) {
    uint32_t a;
    asm("{ .reg .u64 t; cvta.to.shared.u64 t, %1; cvt.u32.u64 %0, t; }" : "=r"(a) : "l"(p));
    return a;
}
__device__ __forceinline__ void cp16(uint32_t saddr, const void* g) {
    asm volatile("cp.async.cg.shared.global [%0], [%1], 16;" :: "r"(saddr), "l"(g));
}
#define CP_COMMIT() asm volatile("cp.async.commit_group;" ::: "memory")
#define CP_WAIT1()  asm volatile("cp.async.wait_group 1;" ::: "memory")
#define CP_WAIT0()  asm volatile("cp.async.wait_group 0;" ::: "memory")

__device__ __forceinline__ void ldsm4(uint32_t* r, uint32_t a) {
    asm volatile("ldmatrix.sync.aligned.m8n8.x4.shared.b16 {%0,%1,%2,%3}, [%4];"
                 : "=r"(r[0]), "=r"(r[1]), "=r"(r[2]), "=r"(r[3]) : "r"(a));
}
__device__ __forceinline__ void mma16816(float* c, const uint32_t* a, uint32_t b0, uint32_t b1) {
    asm volatile("mma.sync.aligned.m16n8k16.row.col.f32.bf16.bf16.f32 "
                 "{%0,%1,%2,%3}, {%4,%5,%6,%7}, {%8,%9}, {%0,%1,%2,%3};"
                 : "+f"(c[0]), "+f"(c[1]), "+f"(c[2]), "+f"(c[3])
                 : "r"(a[0]), "r"(a[1]), "r"(a[2]), "r"(a[3]), "r"(b0), "r"(b1));
}
__device__ __forceinline__ void split_bf16(float v, __nv_bfloat16& hi, __nv_bfloat16& lo) {
    hi = __float2bfloat16(v);
    lo = __float2bfloat16(v - __bfloat162float(hi));
}
__device__ __forceinline__ uint32_t pack_bf(float a, float b) {
    __nv_bfloat16 x = __float2bfloat16(a), y = __float2bfloat16(b);
    return ((uint32_t)*(uint16_t*)&y << 16) | *(uint16_t*)&x;
}

// ---------------- HMMA split GEMM: C = A3 @ B3^T -----------------------------
// A3 [M,K3], B3 [128-tile,K3] row-major bf16. CTA tile 128x128, BK=64,
// 3-stage cp.async ring (wait_group 1), 8 warps (4x2), m16n8k16 HMMA.
// Epilogues: fp32 (+bias,+gelu,+res) | split-bf16 O3 | fused qkv split.
__global__ void __launch_bounds__(256)
mm_gemm(const __nv_bfloat16* __restrict__ A, const __nv_bfloat16* __restrict__ B,
        int K3,
        float* __restrict__ C, __nv_bfloat16* __restrict__ O3,
        long long ldc, int Ksp,
        const float* __restrict__ bias, const float* __restrict__ res,
        int gelu_f, int qkvm,
        __nv_bfloat16* __restrict__ q3o, __nv_bfloat16* __restrict__ k3o,
        __nv_bfloat16* __restrict__ v3o)
{
    extern __shared__ __align__(1024) char smem[];
    const int STAGE = 32768;                  // A 16KB + B 16KB (128 rows x 128B)

    int tid = threadIdx.x;
    int wid = tid >> 5;
    int l   = tid & 31;
    int mw  = wid & 3;
    int nw  = wid >> 2;

    int bn = blockIdx.x, bm = blockIdx.y;
    A += (size_t)bm * 128 * K3;
    B += (size_t)bn * 128 * K3;

    uint32_t sbase = smem_u32(smem);

    uint32_t t_soff[4]; size_t t_goff[4];
#pragma unroll
    for (int i = 0; i < 4; i++) {
        int id = tid + 256 * i;
        int row = id >> 3, c = id & 7;
        t_soff[i] = (uint32_t)(row * 128 + ((c ^ (row & 7)) << 4));
        t_goff[i] = (size_t)row * K3 + c * 8;
    }
    uint32_t lma[2][4], lmb[4][4];
#pragma unroll
    for (int i = 0; i < 2; i++)
#pragma unroll
        for (int kh = 0; kh < 4; kh++) {
            int row = mw * 32 + i * 16 + (l & 15);
            int c = (l >> 4) + kh * 2;
            lma[i][kh] = (uint32_t)(row * 128 + ((c ^ (row & 7)) << 4));
        }
#pragma unroll
    for (int j2 = 0; j2 < 4; j2++)
#pragma unroll
        for (int kh = 0; kh < 4; kh++) {
            int row = nw * 64 + j2 * 16 + (l & 15);
            int c = (l >> 4) + kh * 2;
            lmb[j2][kh] = (uint32_t)(16384 + row * 128 + ((c ^ (row & 7)) << 4));
        }

    float acc[2][8][4];
#pragma unroll
    for (int i = 0; i < 2; i++)
#pragma unroll
        for (int j = 0; j < 8; j++)
#pragma unroll
            for (int k = 0; k < 4; k++) acc[i][j][k] = 0.f;

    int nk = K3 >> 6;   // BK=64

    auto issue = [&](int ks) {
        if (ks < nk) {
            uint32_t st = sbase + (ks % 3) * STAGE;
            const __nv_bfloat16* Ag = A + (size_t)ks * 64;
            const __nv_bfloat16* Bg = B + (size_t)ks * 64;
#pragma unroll
            for (int i = 0; i < 4; i++) cp16(st + t_soff[i], Ag + t_goff[i]);
#pragma unroll
            for (int i = 0; i < 4; i++) cp16(st + 16384 + t_soff[i], Bg + t_goff[i]);
        }
        CP_COMMIT();
    };

    issue(0); issue(1);

    for (int ks = 0; ks < nk; ks++) {
        CP_WAIT1();
        __syncthreads();
        issue(ks + 2);
        uint32_t st = sbase + (ks % 3) * STAGE;
#pragma unroll
        for (int kh = 0; kh < 4; kh++) {
            uint32_t afr[2][4];
#pragma unroll
            for (int i = 0; i < 2; i++) ldsm4(afr[i], st + lma[i][kh]);
            uint32_t bfr[4][4];
#pragma unroll
            for (int j2 = 0; j2 < 4; j2++) ldsm4(bfr[j2], st + lmb[j2][kh]);
#pragma unroll
            for (int i = 0; i < 2; i++)
#pragma unroll
                for (int j = 0; j < 8; j++) {
                    int j2 = j >> 1, hb = j & 1;
                    mma16816(acc[i][j], afr[i], bfr[j2][hb], bfr[j2][hb + 2]);
                }
        }
    }
    CP_WAIT0();
    __syncthreads();

    // ---- epilogue: regs -> SMEM (transpose) -> coalesced GMEM --------------
    const int pitch = 132;
    float* smf = (float*)smem;
#pragma unroll
    for (int i = 0; i < 2; i++)
#pragma unroll
        for (int j = 0; j < 8; j++) {
            int r = mw * 32 + i * 16 + (l >> 2);
            int c = nw * 64 + j * 8 + (l & 3) * 2;
            *(float2*)&smf[r * pitch + c]       = make_float2(acc[i][j][0], acc[i][j][1]);
            *(float2*)&smf[(r + 8) * pitch + c] = make_float2(acc[i][j][2], acc[i][j][3]);
        }
    __syncthreads();

    if (qkvm) {
        int b = bm >> 3;
        int n0g = (bm & 7) * 128;
        if (bn < 16) {
            // q (bn<8, hi|hi|lo) or k (bn>=8, hi|lo|hi), per-head n-major
            int isq = bn < 8;
            int h0 = (isq ? bn : bn - 8) * 2;
            __nv_bfloat16* dst = isq ? q3o : k3o;
#pragma unroll
            for (int p = 0; p < 8; p++) {
                int row = p * 16 + (tid >> 4);
                int c8 = (tid & 15) * 8;
                __align__(16) __nv_bfloat16 hb[8];
                __align__(16) __nv_bfloat16 lb[8];
#pragma unroll
                for (int i = 0; i < 8; i++)
                    split_bf16(smf[row * pitch + c8 + i], hb[i], lb[i]);
                int hh = h0 + (c8 >> 6), d = c8 & 63;
                size_t base = ((size_t)(b * 16 + hh) * 1024 + n0g + row) * 192 + d;
                if (isq) {
                    *(uint4*)(dst + base)       = *(uint4*)hb;
                    *(uint4*)(dst + base + 64)  = *(uint4*)hb;
                    *(uint4*)(dst + base + 128) = *(uint4*)lb;
                } else {
                    *(uint4*)(dst + base)       = *(uint4*)hb;
                    *(uint4*)(dst + base + 64)  = *(uint4*)lb;
                    *(uint4*)(dst + base + 128) = *(uint4*)hb;
                }
            }
        } else {
            // v: d-major scatter (hi|lo|hi over n-chunks of 1024)
            int h0 = (bn - 16) * 2;
            int c = tid >> 1;                // column 0..127 -> (head, d)
            int ngrp = tid & 1;
            int hh = h0 + (c >> 6), d = c & 63;
            size_t base = ((size_t)(b * 16 + hh) * 64 + d) * 3072;
#pragma unroll
            for (int p = 0; p < 8; p++) {
                int n0 = p * 16 + ngrp * 8;
                __align__(16) __nv_bfloat16 hb[8];
                __align__(16) __nv_bfloat16 lb[8];
#pragma unroll
                for (int i = 0; i < 8; i++)
                    split_bf16(smf[(n0 + i) * pitch + c], hb[i], lb[i]);
                size_t ci = base + n0g + n0;
                *(uint4*)(v3o + ci)        = *(uint4*)hb;
                *(uint4*)(v3o + ci + 1024) = *(uint4*)lb;
                *(uint4*)(v3o + ci + 2048) = *(uint4*)hb;
            }
        }
        return;
    }

    int m0 = bm * 128;
#pragma unroll
    for (int p = 0; p < 8; p++) {
        int row = p * 16 + (tid >> 4);
        int c8 = (tid & 15) * 8;
        float vals[8];
#pragma unroll
        for (int i = 0; i < 8; i++) vals[i] = smf[row * pitch + c8 + i];
#pragma unroll
        for (int i = 0; i < 8; i++) {
            float v = vals[i];
            if (bias) v += bias[bn * 128 + c8 + i];
            if (gelu_f) v = 0.5f * v * (1.f + erff(v * 0.70710678118654752f));
            vals[i] = v;
        }
        size_t ci = (size_t)(m0 + row) * ldc + bn * 128 + c8;
        if (O3) {
            __align__(16) __nv_bfloat16 hb[8];
            __align__(16) __nv_bfloat16 lb[8];
#pragma unroll
            for (int i = 0; i < 8; i++) split_bf16(vals[i], hb[i], lb[i]);
            *(uint4*)(O3 + ci)                   = *(uint4*)hb;
            *(uint4*)(O3 + ci + (size_t)Ksp)     = *(uint4*)hb;
            *(uint4*)(O3 + ci + 2 * (size_t)Ksp) = *(uint4*)lb;
        } else {
            if (res) {
                float4 r1 = *(const float4*)(res + ci);
                float4 r2 = *(const float4*)(res + ci + 4);
                vals[0] += r1.x; vals[1] += r1.y; vals[2] += r1.z; vals[3] += r1.w;
                vals[4] += r2.x; vals[5] += r2.y; vals[6] += r2.z; vals[7] += r2.w;
            }
            *(float4*)(C + ci)     = make_float4(vals[0], vals[1], vals[2], vals[3]);
            *(float4*)(C + ci + 4) = make_float4(vals[4], vals[5], vals[6], vals[7]);
        }
    }
}

// ---------------- flash attention: o23 = softmax(0.125*Q K^T) V --------------
#define FA_Q    0u
#define FA_K0   49152u
#define FA_K1   98304u
#define FA_V0   147456u
#define FA_V1   180224u
#define FA_STAT 212992u
#define FA_SMEM 215040

__global__ void __launch_bounds__(256)
flash_attn(const __nv_bfloat16* __restrict__ q3,
           const __nv_bfloat16* __restrict__ k3,
           const __nv_bfloat16* __restrict__ vT3,
           __nv_bfloat16* __restrict__ o23)
{
    extern __shared__ __align__(1024) char smem[];
    uint32_t sb = smem_u32(smem);
    int tid = threadIdx.x, wid = tid >> 5, l = tid & 31;
    int mw = wid & 3, nw = wid >> 2;
    int qt = blockIdx.x, bh = blockIdx.y;
    int b = bh >> 4, h = bh & 15;

    const __nv_bfloat16* Q = q3 + (size_t)bh * 196608 + (size_t)qt * 128 * 192;
    const __nv_bfloat16* K = k3 + (size_t)bh * 196608;
    const __nv_bfloat16* V = vT3 + (size_t)bh * 196608;

    auto load_qk = [&](uint32_t sdst, const __nv_bfloat16* g) {
#pragma unroll
        for (int it = 0; it < 12; it++) {
            int seg = tid + 256 * it;
            int ch = seg >> 9, u = seg & 511, row = u >> 2, c = u & 3;
            cp16(sdst + ch * 8192 + row * 64 + ((c ^ (row & 3)) << 4),
                 g + (size_t)row * 192 + ch * 32 + c * 8);
        }
    };
    auto load_v = [&](uint32_t sdst, int j) {
#pragma unroll
        for (int it = 0; it < 8; it++) {
            int seg = tid + 256 * it;
            int half = seg >> 10, u = seg & 1023;
            int ch = u >> 8, w = u & 255, row = w >> 2, c = w & 3;
            cp16(sdst + half * 16384 + ch * 4096 + row * 64 + ((c ^ (row & 3)) << 4),
                 V + (size_t)row * 3072 + half * 1024 + j * 128 + ch * 32 + c * 8);
        }
    };

    load_qk(sb + FA_Q, Q);
    load_qk(sb + FA_K0, K);
    load_v(sb + FA_V0, 0);
    CP_COMMIT();
    CP_WAIT0();
    __syncthreads();

    float oacc[2][8][4];
#pragma unroll
    for (int i = 0; i < 2; i++)
#pragma unroll
        for (int j = 0; j < 8; j++)
#pragma unroll
            for (int k = 0; k < 4; k++) oacc[i][j][k] = 0.f;
    float m_slot[4], l_slot[4];
#pragma unroll
    for (int s = 0; s < 4; s++) { m_slot[s] = -1e30f; l_slot[s] = 0.f; }

    float* smax = (float*)(smem + FA_STAT);
    float* ssum = smax + 256;
    int rbase = mw * 32 + (l >> 2);

    for (int j = 0; j < 8; j++) {
        uint32_t kbuf = sb + ((j & 1) ? FA_K1 : FA_K0);
        uint32_t vbuf = sb + ((j & 1) ? FA_V1 : FA_V0);
        if (j < 7) {
            load_qk(sb + (((j + 1) & 1) ? FA_K1 : FA_K0), K + (size_t)(j + 1) * 128 * 192);
            load_v(sb + (((j + 1) & 1) ? FA_V1 : FA_V0), j + 1);
        }
        CP_COMMIT();

        float sacc[2][8][4];
#pragma unroll
        for (int i = 0; i < 2; i++)
#pragma unroll
            for (int jj = 0; jj < 8; jj++)
#pragma unroll
                for (int k = 0; k < 4; k++) sacc[i][jj][k] = 0.f;

#pragma unroll
        for (int ch = 0; ch < 6; ch++) {
#pragma unroll
            for (int kh = 0; kh < 2; kh++) {
                uint32_t afr[2][4], bfr[4][4];
#pragma unroll
                for (int i = 0; i < 2; i++) {
                    int row = mw * 32 + i * 16 + (l & 15);
                    int c = (l >> 4) + kh * 2;
                    ldsm4(afr[i], sb + FA_Q + ch * 8192 + row * 64 + ((c ^ (row & 3)) << 4));
                }
#pragma unroll
                for (int j2 = 0; j2 < 4; j2++) {
                    int row = nw * 64 + j2 * 16 + (l & 15);
                    int c = (l >> 4) + kh * 2;
                    ldsm4(bfr[j2], kbuf + ch * 8192 + row * 64 + ((c ^ (row & 3)) << 4));
                }
#pragma unroll
                for (int i = 0; i < 2; i++)
#pragma unroll
                    for (int jj = 0; jj < 8; jj++) {
                        int j2 = jj >> 1, hb = jj & 1;
                        mma16816(sacc[i][jj], afr[i], bfr[j2][hb], bfr[j2][hb + 2]);
                    }
            }
        }

        // ---- online softmax ----
        float mloc[4];
#pragma unroll
        for (int i = 0; i < 2; i++)
#pragma unroll
            for (int h2 = 0; h2 < 2; h2++) {
                float mx = -1e30f;
#pragma unroll
                for (int jj = 0; jj < 8; jj++) {
                    float v0 = sacc[i][jj][h2 * 2] * 0.125f;
                    float v1 = sacc[i][jj][h2 * 2 + 1] * 0.125f;
                    sacc[i][jj][h2 * 2] = v0; sacc[i][jj][h2 * 2 + 1] = v1;
                    mx = fmaxf(mx, fmaxf(v0, v1));
                }
                mx = fmaxf(mx, __shfl_xor_sync(0xffffffffu, mx, 1));
                mx = fmaxf(mx, __shfl_xor_sync(0xffffffffu, mx, 2));
                mloc[i * 2 + h2] = mx;
            }
        if ((l & 3) == 0)
#pragma unroll
            for (int s = 0; s < 4; s++)
                smax[nw * 128 + rbase + (s >> 1) * 16 + (s & 1) * 8] = mloc[s];
        __syncthreads();
        float corr[4];
#pragma unroll
        for (int s = 0; s < 4; s++) {
            int r = rbase + (s >> 1) * 16 + (s & 1) * 8;
            float mt = fmaxf(smax[r], smax[128 + r]);
            float mn = fmaxf(m_slot[s], mt);
            corr[s] = __expf(m_slot[s] - mn);
            m_slot[s] = mn;
        }
        float sloc[4] = {0.f, 0.f, 0.f, 0.f};
#pragma unroll
        for (int i = 0; i < 2; i++)
#pragma unroll
            for (int jj = 0; jj < 8; jj++)
#pragma unroll
                for (int h2 = 0; h2 < 2; h2++) {
                    int s = i * 2 + h2;
                    float p0 = __expf(sacc[i][jj][h2 * 2] - m_slot[s]);
                    float p1 = __expf(sacc[i][jj][h2 * 2 + 1] - m_slot[s]);
                    sacc[i][jj][h2 * 2] = p0; sacc[i][jj][h2 * 2 + 1] = p1;
                    sloc[s] += p0 + p1;
                }
#pragma unroll
        for (int s = 0; s < 4; s++) {
            sloc[s] += __shfl_xor_sync(0xffffffffu, sloc[s], 1);
            sloc[s] += __shfl_xor_sync(0xffffffffu, sloc[s], 2);
        }
        if ((l & 3) == 0)
#pragma unroll
            for (int s = 0; s < 4; s++)
                ssum[nw * 128 + rbase + (s >> 1) * 16 + (s & 1) * 8] = sloc[s];
        __syncthreads();
#pragma unroll
        for (int s = 0; s < 4; s++) {
            int r = rbase + (s >> 1) * 16 + (s & 1) * 8;
            l_slot[s] = l_slot[s] * corr[s] + ssum[r] + ssum[128 + r];
        }
#pragma unroll
        for (int i = 0; i < 2; i++)
#pragma unroll
            for (int jd = 0; jd < 8; jd++)
#pragma unroll
                for (int h2 = 0; h2 < 2; h2++) {
                    oacc[i][jd][h2 * 2]     *= corr[i * 2 + h2];
                    oacc[i][jd][h2 * 2 + 1] *= corr[i * 2 + h2];
                }

        // ---- O += P . V (3-term split) ----
#pragma unroll
        for (int kk = 0; kk < 4; kk++) {
            uint32_t bvh[4][4], bvl[4][4];
            int kh = kk & 1;
            uint32_t choff = (uint32_t)(nw * 2 + (kk >> 1)) * 4096;
#pragma unroll
            for (int j2 = 0; j2 < 4; j2++) {
                int row = j2 * 16 + (l & 15);
                int c = (l >> 4) + kh * 2;
                uint32_t off = (uint32_t)(row * 64 + ((c ^ (row & 3)) << 4));
                ldsm4(bvh[j2], vbuf + choff + off);
                ldsm4(bvl[j2], vbuf + 16384 + choff + off);
            }
#pragma unroll
            for (int i = 0; i < 2; i++) {
                uint32_t ah[4], al[4];
#pragma unroll
                for (int q = 0; q < 4; q++) {
                    int blk = 2 * kk + (q >> 1);
                    int ho = (q & 1) * 2;
                    float p0 = sacc[i][blk][ho], p1 = sacc[i][blk][ho + 1];
                    __nv_bfloat16 h0 = __float2bfloat16(p0), h1 = __float2bfloat16(p1);
                    ah[q] = ((uint32_t)*(uint16_t*)&h1 << 16) | *(uint16_t*)&h0;
                    al[q] = pack_bf(p0 - __bfloat162float(h0), p1 - __bfloat162float(h1));
                }
#pragma unroll
                for (int jd = 0; jd < 8; jd++) {
                    int j2 = jd >> 1, hb = jd & 1;
                    mma16816(oacc[i][jd], ah, bvh[j2][hb], bvh[j2][hb + 2]);
                    mma16816(oacc[i][jd], al, bvh[j2][hb], bvh[j2][hb + 2]);
                    mma16816(oacc[i][jd], ah, bvl[j2][hb], bvl[j2][hb + 2]);
                }
            }
        }
        CP_WAIT0();
        __syncthreads();
    }

    // ---- epilogue ----
    float* om = (float*)smem;
    float* lf = ssum;
    if (nw == 0 && (l & 3) == 0)
#pragma unroll
        for (int s = 0; s < 4; s++)
            lf[rbase + (s >> 1) * 16 + (s & 1) * 8] = l_slot[s];
    if (nw == 1)
#pragma unroll
        for (int i = 0; i < 2; i++)
#pragma unroll
            for (int jd = 0; jd < 8; jd++) {
                int r = mw * 32 + i * 16 + (l >> 2);
                int c = jd * 8 + (l & 3) * 2;
                om[r * 66 + c] = oacc[i][jd][0];
                om[r * 66 + c + 1] = oacc[i][jd][1];
                om[(r + 8) * 66 + c] = oacc[i][jd][2];
                om[(r + 8) * 66 + c + 1] = oacc[i][jd][3];
            }
    __syncthreads();
    if (nw == 0)
#pragma unroll
        for (int i = 0; i < 2; i++)
#pragma unroll
            for (int jd = 0; jd < 8; jd++) {
                int r = mw * 32 + i * 16 + (l >> 2);
                int c = jd * 8 + (l & 3) * 2;
                om[r * 66 + c] += oacc[i][jd][0];
                om[r * 66 + c + 1] += oacc[i][jd][1];
                om[(r + 8) * 66 + c] += oacc[i][jd][2];
                om[(r + 8) * 66 + c + 1] += oacc[i][jd][3];
            }
    __syncthreads();
    size_t rowbase = (size_t)b * 1024 + qt * 128;
#pragma unroll
    for (int p = 0; p < 4; p++) {
        int row = p * 32 + (tid >> 3);
        int c8 = (tid & 7) * 8;
        float inv = 1.f / lf[row];
        __align__(16) __nv_bfloat16 hbv[8];
        __align__(16) __nv_bfloat16 lbv[8];
#pragma unroll
        for (int ii = 0; ii < 8; ii++)
            split_bf16(om[row * 66 + c8 + ii] * inv, hbv[ii], lbv[ii]);
        size_t ci = (rowbase + row) * 3072 + h * 64 + c8;
        *(uint4*)(o23 + ci)        = *(uint4*)hbv;
        *(uint4*)(o23 + ci + 1024) = *(uint4*)hbv;
        *(uint4*)(o23 + ci + 2048) = *(uint4*)lbv;
    }
}

// ---------------- LayerNorm -> split bf16 [hi|hi|lo], K=1024 ----------------
__global__ void ln_split(const float* __restrict__ x, const float* __restrict__ g,
                         const float* __restrict__ b, __nv_bfloat16* __restrict__ out3)
{
    __shared__ float sh1[8], sh2[8];
    int row = blockIdx.x;
    int tid = threadIdx.x;
    const float* p = x + (size_t)row * 1024;
    float v[4];
    float s = 0.f, sq = 0.f;
#pragma unroll
    for (int j = 0; j < 4; j++) {
        v[j] = p[tid + j * 256];
        s += v[j]; sq += v[j] * v[j];
    }
#pragma unroll
    for (int o = 16; o > 0; o >>= 1) {
        s  += __shfl_xor_sync(0xffffffffu, s,  o);
        sq += __shfl_xor_sync(0xffffffffu, sq, o);
    }
    if ((tid & 31) == 0) { sh1[tid >> 5] = s; sh2[tid >> 5] = sq; }
    __syncthreads();
    if (tid == 0) {
        float a = 0.f, c = 0.f;
        for (int i = 0; i < 8; i++) { a += sh1[i]; c += sh2[i]; }
        sh1[0] = a; sh2[0] = c;
    }
    __syncthreads();
    float mean = sh1[0] * (1.f / 1024.f);
    float var  = sh2[0] * (1.f / 1024.f) - mean * mean;
    float rstd = rsqrtf(var + 1e-5f);
    __nv_bfloat16* q = out3 + (size_t)row * 3072;
#pragma unroll
    for (int j = 0; j < 4; j++) {
        int i = tid + j * 256;
        float val = (v[j] - mean) * rstd * g[i] + b[i];
        __nv_bfloat16 hi, lo; split_bf16(val, hi, lo);
        q[i] = hi; q[1024 + i] = hi; q[2048 + i] = lo;
    }
}

// ---------------- weight fp32 [R,K] -> split bf16 [hi|lo|hi] (B-side) -------
__global__ void conv_w3(const float* __restrict__ Wm, __nv_bfloat16* __restrict__ W3,
                        int K, int total)
{
    int idx = blockIdx.x * 256 + threadIdx.x;
    if (idx >= total) return;
    int r = idx / K, k = idx - r * K;
    __nv_bfloat16 hi, lo; split_bf16(Wm[idx], hi, lo);
    size_t base = (size_t)r * 3 * K + k;
    W3[base] = hi; W3[base + K] = lo; W3[base + 2 * K] = hi;
}

// ---------------- template banks -> split bf16 (B-side) ---------------------
__global__ void bank_split(const float* __restrict__ tpl, const float* __restrict__ coef,
                           __nv_bfloat16* __restrict__ W3, int K, int total)
{
    int idx = blockIdx.x * 256 + threadIdx.x;
    if (idx >= total) return;
    float acc = 0.f;
#pragma unroll
    for (int t = 0; t < 16; t++) {
        float ct = 0.5f * (coef[t] + coef[16 + t]);
        acc += tpl[(size_t)t * total + idx] * ct;
    }
    int r = idx / K, k = idx - r * K;
    __nv_bfloat16 hi, lo; split_bf16(acc, hi, lo);
    size_t base = (size_t)r * 3 * K + k;
    W3[base] = hi; W3[base + K] = lo; W3[base + 2 * K] = hi;
}

// ---------------- launcher --------------------------------------------------
extern "C" void kernel_launch(void* const* d_in, const int* in_sizes, int n_in,
                              void* d_out, int out_size)
{
    const float* x      = (const float*)d_in[0];
    const float* ln1_g  = (const float*)d_in[1];
    const float* ln1_b  = (const float*)d_in[2];
    const float* qkv_w  = (const float*)d_in[3];
    const float* proj_w = (const float*)d_in[4];
    const float* proj_b = (const float*)d_in[5];
    const float* ln2_g  = (const float*)d_in[6];
    const float* ln2_b  = (const float*)d_in[7];
    const float* tpl1   = (const float*)d_in[8];
    const float* cf1    = (const float*)d_in[9];
    const float* bias1  = (const float*)d_in[10];
    const float* tpl2   = (const float*)d_in[11];
    const float* cf2    = (const float*)d_in[12];
    const float* bias2  = (const float*)d_in[13];
    float* out = (float*)d_out;

    __nv_bfloat16 *ph3, *pwqkv3, *pwproj3, *pw13, *pw23, *pq3, *pk3, *pvT3, *po23, *py3;
    cudaGetSymbolAddress((void**)&ph3,    g_h3);
    cudaGetSymbolAddress((void**)&pwqkv3, g_wqkv3);
    cudaGetSymbolAddress((void**)&pwproj3,g_wproj3);
    cudaGetSymbolAddress((void**)&pw13,   g_w13);
    cudaGetSymbolAddress((void**)&pw23,   g_w23);
    cudaGetSymbolAddress((void**)&pq3,    g_q3);
    cudaGetSymbolAddress((void**)&pk3,    g_k3);
    cudaGetSymbolAddress((void**)&pvT3,   g_vT3);
    cudaGetSymbolAddress((void**)&po23,   g_o23);
    cudaGetSymbolAddress((void**)&py3,    g_y3);

    const int SMG = 3 * 32768;     // 98304: 3-stage ring (> 67.6KB epilogue buf)
    cudaFuncSetAttribute(mm_gemm, cudaFuncAttributeMaxDynamicSharedMemorySize, SMG);
    cudaFuncSetAttribute(flash_attn, cudaFuncAttributeMaxDynamicSharedMemorySize, FA_SMEM);

    // 1. LN1(x) -> h3 ;  qkv weights
    ln_split<<<8192, 256>>>(x, ln1_g, ln1_b, ph3);
    conv_w3<<<(3072 * 1024 + 255) / 256, 256>>>(qkv_w, pwqkv3, 1024, 3072 * 1024);

    // 2. qkv GEMM with fused q3/k3/vT3 split epilogue
    mm_gemm<<<dim3(24, 64), 256, SMG>>>(
        ph3, pwqkv3, 3072, nullptr, nullptr, 0, 0, nullptr, nullptr, 0,
        1, pq3, pk3, pvT3);

    // 3. fused attention -> o23 (split)
    flash_attn<<<dim3(8, 128), 256, FA_SMEM>>>(pq3, pk3, pvT3, po23);

    // 4. proj weights + out = x + o23 @ wproj3^T + proj_b
    conv_w3<<<(1024 * 1024 + 255) / 256, 256>>>(proj_w, pwproj3, 1024, 1024 * 1024);
    mm_gemm<<<dim3(8, 64), 256, SMG>>>(
        po23, pwproj3, 3072, out, nullptr, 1024, 0, proj_b, x, 0,
        0, nullptr, nullptr, nullptr);

    // 5. LN2(out) -> h3 ; MLP banks
    ln_split<<<8192, 256>>>(out, ln2_g, ln2_b, ph3);
    bank_split<<<(4096 * 1024 + 255) / 256, 256>>>(tpl1, cf1, pw13, 1024, 4096 * 1024);
    bank_split<<<(1024 * 4096 + 255) / 256, 256>>>(tpl2, cf2, pw23, 4096, 1024 * 4096);

    // 6. y3(split) = gelu(h3 @ w13^T + bias1)  [8192,4096]
    mm_gemm<<<dim3(32, 64), 256, SMG>>>(
        ph3, pw13, 3072, nullptr, py3, 12288, 4096, bias1, nullptr, 1,
        0, nullptr, nullptr, nullptr);

    // 7. out = out + y3 @ w23^T + bias2
    mm_gemm<<<dim3(8, 64), 256, SMG>>>(
        py3, pw23, 12288, out, nullptr, 1024, 0, bias2, out, 0,
        0, nullptr, nullptr, nullptr);
}